// round 6
// baseline (speedup 1.0000x reference)
#include <cuda_runtime.h>
#include <math.h>
#include <stdint.h>

#define BATCH 2
#define SEQ   2048
#define EMB   1024
#define NHEADS 16
#define HDIM  64
#define FF    4096
#define MTOT  (BATCH*SEQ)   /* 4096 rows */
#define QKVN  (3*EMB)       /* 3072 */

__device__ __forceinline__ uint32_t smem_u32(const void* p) {
    uint32_t a;
    asm("{ .reg .u64 t; cvta.to.shared.u64 t, %1; cvt.u32.u64 %0, t; }" : "=r"(a) : "l"(p));
    return a;
}
__device__ __forceinline__ uint32_t f2tf32(float x) {
    uint32_t y;
    asm("cvt.rna.tf32.f32 %0, %1;" : "=r"(y) : "f"(x));
    return y;
}
__device__ __forceinline__ float f2tf32f(float x) { return __uint_as_float(f2tf32(x)); }
__device__ __forceinline__ void mma_tf32(float c[4],
    uint32_t a0, uint32_t a1, uint32_t a2, uint32_t a3,
    uint32_t b0, uint32_t b1)
{
    asm volatile("mma.sync.aligned.m16n8k8.row.col.f32.tf32.tf32.f32 "
        "{%0,%1,%2,%3}, {%4,%5,%6,%7}, {%8,%9}, {%0,%1,%2,%3};"
        : "+f"(c[0]), "+f"(c[1]), "+f"(c[2]), "+f"(c[3])
        : "r"(a0), "r"(a1), "r"(a2), "r"(a3), "r"(b0), "r"(b1));
}
__device__ __forceinline__ void cp_async16(uint32_t saddr, const void* gptr) {
    asm volatile("cp.async.cg.shared.global [%0], [%1], 16;" :: "r"(saddr), "l"(gptr));
}
__device__ __forceinline__ void cp_commit() { asm volatile("cp.async.commit_group;" ::: "memory"); }
template<int N> __device__ __forceinline__ void cp_wait() {
    asm volatile("cp.async.wait_group %0;" :: "n"(N) : "memory");
}

// ================= scratch (device globals) =================
__device__ float g_h  [MTOT*EMB];
__device__ float g_qkv[(size_t)MTOT*QKVN];
__device__ float g_ctx[MTOT*EMB];
__device__ float g_x2 [MTOT*EMB];
__device__ float g_ff [(size_t)MTOT*FF];
__device__ uint32_t g_wtqkv[(size_t)QKVN*EMB];
__device__ uint32_t g_wto[EMB*EMB];
__device__ uint32_t g_wt1[(size_t)FF*EMB];
__device__ uint32_t g_wt2[(size_t)EMB*FF];
__device__ float g_bqkv[QKVN];

// ================= LayerNorm (ddof=1), output tf32-rounded =================
__global__ __launch_bounds__(256)
void ln_kernel(const float* __restrict__ x, const float* __restrict__ sc,
               const float* __restrict__ sh, float* __restrict__ out)
{
    int row = blockIdx.x;
    const float* xr = x + (size_t)row * EMB;
    int t = threadIdx.x;
    float4 v4 = *(const float4*)(xr + t * 4);
    float v[4] = {v4.x, v4.y, v4.z, v4.w};
    __shared__ float red[8];
    float s = v[0] + v[1] + v[2] + v[3];
    #pragma unroll
    for (int o = 16; o; o >>= 1) s += __shfl_xor_sync(0xffffffffu, s, o);
    if ((t & 31) == 0) red[t >> 5] = s;
    __syncthreads();
    float tot = 0.f;
    #pragma unroll
    for (int i = 0; i < 8; i++) tot += red[i];
    float mean = tot * (1.0f / EMB);
    __syncthreads();
    float sq = 0.f;
    #pragma unroll
    for (int i = 0; i < 4; i++) { float d = v[i] - mean; sq += d * d; }
    #pragma unroll
    for (int o = 16; o; o >>= 1) sq += __shfl_xor_sync(0xffffffffu, sq, o);
    if ((t & 31) == 0) red[t >> 5] = sq;
    __syncthreads();
    float sqt = 0.f;
    #pragma unroll
    for (int i = 0; i < 8; i++) sqt += red[i];
    float rstd = rsqrtf(sqt * (1.0f / (EMB - 1)) + 1e-5f);
    float4 o4; float* ov = &o4.x;
    #pragma unroll
    for (int i = 0; i < 4; i++) {
        int c = t * 4 + i;
        ov[i] = f2tf32f(sc[c] * (v[i] - mean) * rstd + sh[c]);
    }
    *(float4*)(out + (size_t)row * EMB + t * 4) = o4;
}

// ================= weight transpose + tf32 round =================
__global__ __launch_bounds__(256)
void transpose_tf32(const float* __restrict__ W, uint32_t* __restrict__ Wt, int K, int N)
{
    __shared__ float tile[32][33];
    int x0 = blockIdx.x * 32, y0 = blockIdx.y * 32;
    int tx = threadIdx.x, ty = threadIdx.y;
    #pragma unroll
    for (int j = 0; j < 32; j += 8)
        tile[ty + j][tx] = W[(size_t)(y0 + ty + j) * N + x0 + tx];
    __syncthreads();
    #pragma unroll
    for (int j = 0; j < 32; j += 8)
        Wt[(size_t)(x0 + ty + j) * K + y0 + tx] = f2tf32(tile[tx][ty + j]);
}

__global__ void concat_bias(const float* a, const float* b, const float* c, float* out)
{
    int i = blockIdx.x * 256 + threadIdx.x;
    if (i < EMB)            out[i] = a[i];
    else if (i < 2 * EMB)   out[i] = b[i - EMB];
    else if (i < 3 * EMB)   out[i] = c[i - 2 * EMB];
}

// ================= tf32 mma.sync GEMM, 4-stage cp.async =================
// C[M,N] = A[M,K] @ Wt[N,K]^T + bias (+res | gelu).
// CTA tile 256x128, BK=16; 8 warps (4M x 2N), warp tile 64x64.
// mode 0: +bias, round out   1: +bias+res, fp32 out   2: gelu(+bias), round out
#define ROWPAD 20
#define A_STAGE_F (256*ROWPAD)
#define B_STAGE_F (128*ROWPAD)
#define STAGE_F   (A_STAGE_F + B_STAGE_F)
#define GEMM_SMEM (4*STAGE_F*4)            /* 122880 bytes */

__global__ __launch_bounds__(256, 1)
void tc_gemm(const float* __restrict__ A, const uint32_t* __restrict__ Bt,
             const float* __restrict__ bias, const float* __restrict__ res,
             float* __restrict__ C, int M, int N, int K, int mode)
{
    extern __shared__ float smf[];
    uint32_t sb = smem_u32(smf);

    int tid  = threadIdx.x;
    int lane = tid & 31, wid = tid >> 5;
    int g    = lane >> 2;
    int kq   = lane & 3;
    int wm   = wid & 3;            // 4 M-warps (64 rows each)
    int wn   = wid >> 2;           // 2 N-warps (64 cols each)
    int bcol = blockIdx.x * 128, brow = blockIdx.y * 256;

    const float*    Ap = A  + (size_t)brow * K;
    const uint32_t* Bp = Bt + (size_t)bcol * K;

    // per-thread cp.async coords: A 4 float4 (256x16), B 2 float4 (128x16)
    int ar[4], ac[4], br[2], bc[2];
    #pragma unroll
    for (int u = 0; u < 4; u++) {
        int idx = tid + u * 256;
        ar[u] = idx >> 2;            // 0..255
        ac[u] = (idx & 3) * 4;
    }
    #pragma unroll
    for (int u = 0; u < 2; u++) {
        int idx = tid + u * 256;
        br[u] = idx >> 2;            // 0..127
        bc[u] = (idx & 3) * 4;
    }

    float acc[4][8][4];
    #pragma unroll
    for (int mi = 0; mi < 4; mi++)
        #pragma unroll
        for (int ni = 0; ni < 8; ni++)
            #pragma unroll
            for (int e = 0; e < 4; e++) acc[mi][ni][e] = 0.f;

    int nk = K >> 4;

    // prologue: stages 0..2
    #pragma unroll
    for (int s = 0; s < 3; s++) {
        uint32_t abase = sb + (uint32_t)(s * STAGE_F) * 4;
        uint32_t bbase = abase + A_STAGE_F * 4;
        const float*    Ag = Ap + s * 16;
        const uint32_t* Bg = Bp + s * 16;
        #pragma unroll
        for (int u = 0; u < 4; u++)
            cp_async16(abase + (uint32_t)(ar[u] * ROWPAD + ac[u]) * 4, Ag + (size_t)ar[u] * K + ac[u]);
        #pragma unroll
        for (int u = 0; u < 2; u++)
            cp_async16(bbase + (uint32_t)(br[u] * ROWPAD + bc[u]) * 4, Bg + (size_t)br[u] * K + bc[u]);
        cp_commit();
    }

    #pragma unroll 1
    for (int kt = 0; kt < nk; kt++) {
        cp_wait<2>();
        __syncthreads();

        if (kt + 3 < nk) {
            int s = (kt + 3) & 3;
            uint32_t abase = sb + (uint32_t)(s * STAGE_F) * 4;
            uint32_t bbase = abase + A_STAGE_F * 4;
            const float*    Ag = Ap + (kt + 3) * 16;
            const uint32_t* Bg = Bp + (kt + 3) * 16;
            #pragma unroll
            for (int u = 0; u < 4; u++)
                cp_async16(abase + (uint32_t)(ar[u] * ROWPAD + ac[u]) * 4, Ag + (size_t)ar[u] * K + ac[u]);
            #pragma unroll
            for (int u = 0; u < 2; u++)
                cp_async16(bbase + (uint32_t)(br[u] * ROWPAD + bc[u]) * 4, Bg + (size_t)br[u] * K + bc[u]);
        }
        cp_commit();

        const float* As = smf + (kt & 3) * STAGE_F;
        const float* Bs = As + A_STAGE_F;
        #pragma unroll
        for (int ks = 0; ks < 2; ks++) {
            int k0 = ks * 8 + kq;
            uint32_t af[4][4];
            #pragma unroll
            for (int mi = 0; mi < 4; mi++) {
                const float* ap = As + (wm * 64 + mi * 16 + g) * ROWPAD;
                af[mi][0] = __float_as_uint(ap[k0]);
                af[mi][1] = __float_as_uint(ap[8 * ROWPAD + k0]);
                af[mi][2] = __float_as_uint(ap[k0 + 4]);
                af[mi][3] = __float_as_uint(ap[8 * ROWPAD + k0 + 4]);
            }
            uint32_t bf[8][2];
            #pragma unroll
            for (int ni = 0; ni < 8; ni++) {
                const float* bp = Bs + (wn * 64 + ni * 8 + g) * ROWPAD;
                bf[ni][0] = __float_as_uint(bp[k0]);
                bf[ni][1] = __float_as_uint(bp[k0 + 4]);
            }
            #pragma unroll
            for (int mi = 0; mi < 4; mi++)
                #pragma unroll
                for (int ni = 0; ni < 8; ni++)
                    mma_tf32(acc[mi][ni], af[mi][0], af[mi][1], af[mi][2], af[mi][3],
                             bf[ni][0], bf[ni][1]);
        }
    }

    // epilogue
    #pragma unroll
    for (int mi = 0; mi < 4; mi++) {
        #pragma unroll
        for (int ni = 0; ni < 8; ni++) {
            int row = brow + wm * 64 + mi * 16 + g;
            int col = bcol + wn * 64 + ni * 8 + 2 * kq;
            #pragma unroll
            for (int half = 0; half < 2; half++) {
                int r = row + half * 8;
                float v0 = acc[mi][ni][half * 2 + 0] + bias[col];
                float v1 = acc[mi][ni][half * 2 + 1] + bias[col + 1];
                if (mode == 1) {
                    v0 += res[(size_t)r * N + col];
                    v1 += res[(size_t)r * N + col + 1];
                } else if (mode == 2) {
                    float x0 = v0, x1 = v1;
                    v0 = 0.5f * x0 * (1.f + tanhf(0.7978845608028654f *
                                                  (x0 + 0.044715f * x0 * x0 * x0)));
                    v1 = 0.5f * x1 * (1.f + tanhf(0.7978845608028654f *
                                                  (x1 + 0.044715f * x1 * x1 * x1)));
                }
                if (mode != 1) { v0 = f2tf32f(v0); v1 = f2tf32f(v1); }
                float2 o2 = { v0, v1 };
                *(float2*)(C + (size_t)r * N + col) = o2;
            }
        }
    }
}

// ================= Causal flash attention, mma.sync tf32 =================
#define APAD 68
#define ATTN_SMEM ((128+64+64)*APAD*4)

__global__ __launch_bounds__(256)
void attn_mma(const float* __restrict__ QKV, float* __restrict__ O)
{
    extern __shared__ float sm[];
    float* QP = sm;
    float* Ks = sm + 128 * APAD;
    float* Vt = Ks + 64 * APAD;

    int tid = threadIdx.x, lane = tid & 31, w = tid >> 5;
    int g = lane >> 2, kq = lane & 3;
    int qb = blockIdx.x, h = blockIdx.y, b = blockIdx.z;
    size_t base = ((size_t)b * SEQ) * QKVN + h * HDIM;
    size_t obase = ((size_t)b * SEQ) * EMB + h * HDIM;
    int wrow = w * 16;

    #pragma unroll
    for (int u = 0; u < 8; u++) {
        int idx = tid + u * 256;
        int r = idx >> 4, c = (idx & 15) * 4;
        float4 qv = *(const float4*)(QKV + base + (size_t)(qb * 128 + r) * QKVN + c);
        QP[r * APAD + c + 0] = qv.x * 0.125f;
        QP[r * APAD + c + 1] = qv.y * 0.125f;
        QP[r * APAD + c + 2] = qv.z * 0.125f;
        QP[r * APAD + c + 3] = qv.w * 0.125f;
    }
    __syncthreads();

    uint32_t qa[8][4];
    #pragma unroll
    for (int ks = 0; ks < 8; ks++) {
        int k0 = ks * 8 + kq;
        qa[ks][0] = __float_as_uint(QP[(wrow + g)     * APAD + k0]);
        qa[ks][1] = __float_as_uint(QP[(wrow + g + 8) * APAD + k0]);
        qa[ks][2] = __float_as_uint(QP[(wrow + g)     * APAD + k0 + 4]);
        qa[ks][3] = __float_as_uint(QP[(wrow + g + 8) * APAD + k0 + 4]);
    }

    float m0 = -1e30f, m1 = -1e30f, l0 = 0.f, l1 = 0.f;
    float o[8][4];
    #pragma unroll
    for (int ni = 0; ni < 8; ni++)
        #pragma unroll
        for (int e = 0; e < 4; e++) o[ni][e] = 0.f;

    int nkt = 2 * qb + 2;
    #pragma unroll 1
    for (int kb = 0; kb < nkt; kb++) {
        __syncthreads();
        #pragma unroll
        for (int u = 0; u < 4; u++) {
            int idx = tid + u * 256;
            int r = idx >> 4, c = (idx & 15) * 4;
            size_t gk = base + EMB + (size_t)(kb * 64 + r) * QKVN + c;
            float4 kv = *(const float4*)(QKV + gk);
            Ks[r * APAD + c + 0] = kv.x; Ks[r * APAD + c + 1] = kv.y;
            Ks[r * APAD + c + 2] = kv.z; Ks[r * APAD + c + 3] = kv.w;
        }
        #pragma unroll
        for (int u = 0; u < 4; u++) {
            int chunk = tid + u * 256;
            int key = chunk >> 4, dg = (chunk & 15) * 4;
            float4 vv = *(const float4*)(QKV + base + 2 * EMB + (size_t)(kb * 64 + key) * QKVN + dg);
            Vt[(dg + 0) * APAD + key] = vv.x;
            Vt[(dg + 1) * APAD + key] = vv.y;
            Vt[(dg + 2) * APAD + key] = vv.z;
            Vt[(dg + 3) * APAD + key] = vv.w;
        }
        __syncthreads();

        float s[8][4];
        #pragma unroll
        for (int ni = 0; ni < 8; ni++)
            #pragma unroll
            for (int e = 0; e < 4; e++) s[ni][e] = 0.f;
        #pragma unroll
        for (int ks = 0; ks < 8; ks++) {
            int k0 = ks * 8 + kq;
            #pragma unroll
            for (int ni = 0; ni < 8; ni++) {
                uint32_t b0 = __float_as_uint(Ks[(ni * 8 + g) * APAD + k0]);
                uint32_t b1 = __float_as_uint(Ks[(ni * 8 + g) * APAD + k0 + 4]);
                mma_tf32(s[ni], qa[ks][0], qa[ks][1], qa[ks][2], qa[ks][3], b0, b1);
            }
        }

        if (kb >= 2 * qb) {
            int row0 = qb * 128 + wrow + g;
            int row1 = row0 + 8;
            #pragma unroll
            for (int ni = 0; ni < 8; ni++) {
                int col = kb * 64 + ni * 8 + 2 * kq;
                if (col     > row0) s[ni][0] = -1e30f;
                if (col + 1 > row0) s[ni][1] = -1e30f;
                if (col     > row1) s[ni][2] = -1e30f;
                if (col + 1 > row1) s[ni][3] = -1e30f;
            }
        }

        float rm0 = -1e30f, rm1 = -1e30f;
        #pragma unroll
        for (int ni = 0; ni < 8; ni++) {
            rm0 = fmaxf(rm0, fmaxf(s[ni][0], s[ni][1]));
            rm1 = fmaxf(rm1, fmaxf(s[ni][2], s[ni][3]));
        }
        rm0 = fmaxf(rm0, __shfl_xor_sync(0xffffffffu, rm0, 1));
        rm0 = fmaxf(rm0, __shfl_xor_sync(0xffffffffu, rm0, 2));
        rm1 = fmaxf(rm1, __shfl_xor_sync(0xffffffffu, rm1, 1));
        rm1 = fmaxf(rm1, __shfl_xor_sync(0xffffffffu, rm1, 2));
        float mn0 = fmaxf(m0, rm0), mn1 = fmaxf(m1, rm1);
        float a0 = __expf(m0 - mn0), a1 = __expf(m1 - mn1);
        float rs0 = 0.f, rs1 = 0.f;
        #pragma unroll
        for (int ni = 0; ni < 8; ni++) {
            float p0 = __expf(s[ni][0] - mn0);
            float p1 = __expf(s[ni][1] - mn0);
            float p2 = __expf(s[ni][2] - mn1);
            float p3 = __expf(s[ni][3] - mn1);
            rs0 += p0 + p1; rs1 += p2 + p3;
            int col = ni * 8 + 2 * kq;
            float2 t0 = { f2tf32f(p0), f2tf32f(p1) };
            float2 t1 = { f2tf32f(p2), f2tf32f(p3) };
            *(float2*)(QP + (wrow + g)     * APAD + col) = t0;
            *(float2*)(QP + (wrow + g + 8) * APAD + col) = t1;
        }
        rs0 += __shfl_xor_sync(0xffffffffu, rs0, 1);
        rs0 += __shfl_xor_sync(0xffffffffu, rs0, 2);
        rs1 += __shfl_xor_sync(0xffffffffu, rs1, 1);
        rs1 += __shfl_xor_sync(0xffffffffu, rs1, 2);
        l0 = l0 * a0 + rs0;
        l1 = l1 * a1 + rs1;
        m0 = mn0; m1 = mn1;
        #pragma unroll
        for (int ni = 0; ni < 8; ni++) {
            o[ni][0] *= a0; o[ni][1] *= a0;
            o[ni][2] *= a1; o[ni][3] *= a1;
        }
        __syncwarp();

        #pragma unroll
        for (int ks2 = 0; ks2 < 8; ks2++) {
            int k0 = ks2 * 8 + kq;
            uint32_t pa0 = __float_as_uint(QP[(wrow + g)     * APAD + k0]);
            uint32_t pa1 = __float_as_uint(QP[(wrow + g + 8) * APAD + k0]);
            uint32_t pa2 = __float_as_uint(QP[(wrow + g)     * APAD + k0 + 4]);
            uint32_t pa3 = __float_as_uint(QP[(wrow + g + 8) * APAD + k0 + 4]);
            #pragma unroll
            for (int ni = 0; ni < 8; ni++) {
                uint32_t b0 = __float_as_uint(Vt[(ni * 8 + g) * APAD + k0]);
                uint32_t b1 = __float_as_uint(Vt[(ni * 8 + g) * APAD + k0 + 4]);
                mma_tf32(o[ni], pa0, pa1, pa2, pa3, b0, b1);
            }
        }
    }

    float inv0 = 1.0f / l0, inv1 = 1.0f / l1;
    size_t row0 = obase + (size_t)(qb * 128 + wrow + g) * EMB;
    size_t row1 = row0 + (size_t)8 * EMB;
    #pragma unroll
    for (int ni = 0; ni < 8; ni++) {
        int col = ni * 8 + 2 * kq;
        float2 q0 = { f2tf32f(o[ni][0] * inv0), f2tf32f(o[ni][1] * inv0) };
        float2 q1 = { f2tf32f(o[ni][2] * inv1), f2tf32f(o[ni][3] * inv1) };
        *(float2*)(O + row0 + col) = q0;
        *(float2*)(O + row1 + col) = q1;
    }
}

// ================= launch =================
extern "C" void kernel_launch(void* const* d_in, const int* in_sizes, int n_in,
                              void* d_out, int out_size)
{
    const float* x         = (const float*)d_in[0];
    const float* Wq        = (const float*)d_in[1];
    const float* bq        = (const float*)d_in[2];
    const float* Wk        = (const float*)d_in[3];
    const float* bk        = (const float*)d_in[4];
    const float* Wv        = (const float*)d_in[5];
    const float* bv        = (const float*)d_in[6];
    const float* Wo        = (const float*)d_in[7];
    const float* bo        = (const float*)d_in[8];
    const float* W1        = (const float*)d_in[9];
    const float* b1        = (const float*)d_in[10];
    const float* W2        = (const float*)d_in[11];
    const float* b2        = (const float*)d_in[12];
    const float* ln1_scale = (const float*)d_in[13];
    const float* ln1_shift = (const float*)d_in[14];
    const float* ln2_scale = (const float*)d_in[15];
    const float* ln2_shift = (const float*)d_in[16];
    float* out = (float*)d_out;

    float *h, *qkv, *ctx, *x2, *ff, *bqkv;
    uint32_t *wtqkv, *wto, *wt1, *wt2;
    cudaGetSymbolAddress((void**)&h,     g_h);
    cudaGetSymbolAddress((void**)&qkv,   g_qkv);
    cudaGetSymbolAddress((void**)&ctx,   g_ctx);
    cudaGetSymbolAddress((void**)&x2,    g_x2);
    cudaGetSymbolAddress((void**)&ff,    g_ff);
    cudaGetSymbolAddress((void**)&bqkv,  g_bqkv);
    cudaGetSymbolAddress((void**)&wtqkv, g_wtqkv);
    cudaGetSymbolAddress((void**)&wto,   g_wto);
    cudaGetSymbolAddress((void**)&wt1,   g_wt1);
    cudaGetSymbolAddress((void**)&wt2,   g_wt2);

    cudaFuncSetAttribute(tc_gemm,  cudaFuncAttributeMaxDynamicSharedMemorySize, GEMM_SMEM);
    cudaFuncSetAttribute(attn_mma, cudaFuncAttributeMaxDynamicSharedMemorySize, ATTN_SMEM);

    dim3 tb(32, 8);
    dim3 gQKV(QKVN / 128, MTOT / 256);
    dim3 gE  (EMB  / 128, MTOT / 256);
    dim3 gF  (FF   / 128, MTOT / 256);
    dim3 gA  (SEQ / 128, NHEADS, BATCH);

    // launch order arranged so launch index 5 (ncu -s 5 -c 1) = QKV tc_gemm
    transpose_tf32<<<dim3(EMB/32, EMB/32), tb>>>(Wq, wtqkv,                     EMB, EMB);  // 0
    transpose_tf32<<<dim3(EMB/32, EMB/32), tb>>>(Wk, wtqkv + (size_t)EMB*EMB,   EMB, EMB);  // 1
    transpose_tf32<<<dim3(EMB/32, EMB/32), tb>>>(Wv, wtqkv + (size_t)2*EMB*EMB, EMB, EMB);  // 2
    concat_bias<<<(QKVN + 255)/256, 256>>>(bq, bk, bv, bqkv);                               // 3
    ln_kernel<<<MTOT, 256>>>(x, ln1_scale, ln1_shift, h);                                   // 4
    tc_gemm<<<gQKV, 256, GEMM_SMEM>>>(h, wtqkv, bqkv, nullptr, qkv, MTOT, QKVN, EMB, 0);    // 5 <- profiled
    transpose_tf32<<<dim3(EMB/32, EMB/32), tb>>>(Wo, wto, EMB, EMB);                        // 6
    transpose_tf32<<<dim3(FF/32,  EMB/32), tb>>>(W1, wt1, EMB, FF);                         // 7
    transpose_tf32<<<dim3(EMB/32, FF/32),  tb>>>(W2, wt2, FF, EMB);                         // 8
    attn_mma<<<gA, 256, ATTN_SMEM>>>(qkv, ctx);                                             // 9
    tc_gemm<<<gE, 256, GEMM_SMEM>>>(ctx, wto, bo, x, x2, MTOT, EMB, EMB, 1);                // 10
    ln_kernel<<<MTOT, 256>>>(x2, ln2_scale, ln2_shift, h);                                  // 11
    tc_gemm<<<gF, 256, GEMM_SMEM>>>(h, wt1, b1, nullptr, ff, MTOT, FF, EMB, 2);             // 12
    tc_gemm<<<gE, 256, GEMM_SMEM>>>(ff, wt2, b2, x2, out, MTOT, EMB, FF, 1);                // 13
}

// round 7
// speedup vs baseline: 1.8369x; 1.8369x over previous
#include <cuda_runtime.h>
#include <cuda_fp16.h>
#include <math.h>
#include <stdint.h>

#define BATCH 2
#define SEQ   2048
#define EMB   1024
#define NHEADS 16
#define HDIM  64
#define FF    4096
#define MTOT  (BATCH*SEQ)   /* 4096 rows */
#define QKVN  (3*EMB)       /* 3072 */

__device__ __forceinline__ uint32_t smem_u32(const void* p) {
    uint32_t a;
    asm("{ .reg .u64 t; cvta.to.shared.u64 t, %1; cvt.u32.u64 %0, t; }" : "=r"(a) : "l"(p));
    return a;
}
__device__ __forceinline__ void mma_f16(float c[4],
    uint32_t a0, uint32_t a1, uint32_t a2, uint32_t a3,
    uint32_t b0, uint32_t b1)
{
    asm volatile("mma.sync.aligned.m16n8k16.row.col.f32.f16.f16.f32 "
        "{%0,%1,%2,%3}, {%4,%5,%6,%7}, {%8,%9}, {%0,%1,%2,%3};"
        : "+f"(c[0]), "+f"(c[1]), "+f"(c[2]), "+f"(c[3])
        : "r"(a0), "r"(a1), "r"(a2), "r"(a3), "r"(b0), "r"(b1));
}
__device__ __forceinline__ void cp_async16(uint32_t saddr, const void* gptr) {
    asm volatile("cp.async.cg.shared.global [%0], [%1], 16;" :: "r"(saddr), "l"(gptr));
}
__device__ __forceinline__ void cp_commit() { asm volatile("cp.async.commit_group;" ::: "memory"); }
template<int N> __device__ __forceinline__ void cp_wait() {
    asm volatile("cp.async.wait_group %0;" :: "n"(N) : "memory");
}
__device__ __forceinline__ uint32_t pack_h2(float a, float b) {
    __half2 h = __floats2half2_rn(a, b);
    return *reinterpret_cast<uint32_t*>(&h);
}

// ================= scratch (device globals) =================
__device__ __half g_h  [MTOT*EMB];
__device__ __half g_qkv[(size_t)MTOT*QKVN];
__device__ __half g_ctx[MTOT*EMB];
__device__ float  g_x2 [MTOT*EMB];
__device__ __half g_ff [(size_t)MTOT*FF];
__device__ __half g_wtqkv[(size_t)QKVN*EMB];
__device__ __half g_wto[EMB*EMB];
__device__ __half g_wt1[(size_t)FF*EMB];
__device__ __half g_wt2[(size_t)EMB*FF];
__device__ float  g_bqkv[QKVN];

// ================= LayerNorm (ddof=1), half output =================
__global__ __launch_bounds__(256)
void ln_kernel(const float* __restrict__ x, const float* __restrict__ sc,
               const float* __restrict__ sh, __half* __restrict__ out)
{
    int row = blockIdx.x;
    const float* xr = x + (size_t)row * EMB;
    int t = threadIdx.x;
    float4 v4 = *(const float4*)(xr + t * 4);
    float v[4] = {v4.x, v4.y, v4.z, v4.w};
    __shared__ float red[8];
    float s = v[0] + v[1] + v[2] + v[3];
    #pragma unroll
    for (int o = 16; o; o >>= 1) s += __shfl_xor_sync(0xffffffffu, s, o);
    if ((t & 31) == 0) red[t >> 5] = s;
    __syncthreads();
    float tot = 0.f;
    #pragma unroll
    for (int i = 0; i < 8; i++) tot += red[i];
    float mean = tot * (1.0f / EMB);
    __syncthreads();
    float sq = 0.f;
    #pragma unroll
    for (int i = 0; i < 4; i++) { float d = v[i] - mean; sq += d * d; }
    #pragma unroll
    for (int o = 16; o; o >>= 1) sq += __shfl_xor_sync(0xffffffffu, sq, o);
    if ((t & 31) == 0) red[t >> 5] = sq;
    __syncthreads();
    float sqt = 0.f;
    #pragma unroll
    for (int i = 0; i < 8; i++) sqt += red[i];
    float rstd = rsqrtf(sqt * (1.0f / (EMB - 1)) + 1e-5f);
    float r[4];
    #pragma unroll
    for (int i = 0; i < 4; i++) {
        int c = t * 4 + i;
        r[i] = sc[c] * (v[i] - mean) * rstd + sh[c];
    }
    uint2 st = { pack_h2(r[0], r[1]), pack_h2(r[2], r[3]) };
    *(uint2*)(out + (size_t)row * EMB + t * 4) = st;
}

// ================= weight transpose + half round (with scale) =================
__global__ __launch_bounds__(256)
void transpose_half(const float* __restrict__ W, __half* __restrict__ Wt,
                    int K, int N, float scale)
{
    __shared__ float tile[32][33];
    int x0 = blockIdx.x * 32, y0 = blockIdx.y * 32;
    int tx = threadIdx.x, ty = threadIdx.y;
    #pragma unroll
    for (int j = 0; j < 32; j += 8)
        tile[ty + j][tx] = W[(size_t)(y0 + ty + j) * N + x0 + tx];
    __syncthreads();
    #pragma unroll
    for (int j = 0; j < 32; j += 8)
        Wt[(size_t)(x0 + ty + j) * K + y0 + tx] = __float2half(tile[tx][ty + j] * scale);
}

__global__ void concat_bias(const float* a, const float* b, const float* c, float* out)
{
    int i = blockIdx.x * 256 + threadIdx.x;
    if (i < EMB)            out[i] = a[i] * 0.125f;   // fold 1/sqrt(HDIM) into q
    else if (i < 2 * EMB)   out[i] = b[i - EMB];
    else if (i < 3 * EMB)   out[i] = c[i - 2 * EMB];
}

// ================= fp16 mma.sync GEMM, 4-stage cp.async =================
// C[M,N] = A[M,K] @ Wt[N,K]^T + bias (+res | gelu). A,Wt half; accum fp32.
// CTA 128x128, BK=32 halves; 8 warps (2M x 4N), warp tile 64x32.
// mode 0: +bias, half out   1: +bias+res, fp32 out   2: gelu(+bias), half out
#define PADH 40                              /* halves per SMEM row (80B) */
#define TILE_H (128*PADH)                    /* halves per operand per stage */
#define STAGE_B (2*TILE_H*2)                 /* bytes per stage: 20480 */
#define GEMM_SMEM (4*STAGE_B)                /* 81920 */

__global__ __launch_bounds__(256, 2)
void tc_gemm(const __half* __restrict__ A, const __half* __restrict__ Bt,
             const float* __restrict__ bias, const float* __restrict__ res,
             void* __restrict__ Cv, int M, int N, int K, int mode)
{
    extern __shared__ __half smh[];
    uint32_t sb = smem_u32(smh);

    int tid  = threadIdx.x;
    int lane = tid & 31, wid = tid >> 5;
    int g    = lane >> 2;
    int kq   = lane & 3;
    int wm   = wid & 1;
    int wn   = wid >> 1;
    int bcol = blockIdx.x * 128, brow = blockIdx.y * 128;

    const __half* Ap = A  + (size_t)brow * K;
    const __half* Bp = Bt + (size_t)bcol * K;

    // per-thread cp.async coords: 128 rows x 4 chunks(16B) per operand, 2/thread
    int lr[2], lc[2];
    #pragma unroll
    for (int u = 0; u < 2; u++) {
        int idx = tid + u * 256;
        lr[u] = idx >> 2;            // 0..127
        lc[u] = idx & 3;             // chunk 0..3 (16 bytes = 8 halves)
    }

    float acc[4][4][4];
    #pragma unroll
    for (int mi = 0; mi < 4; mi++)
        #pragma unroll
        for (int ni = 0; ni < 4; ni++)
            #pragma unroll
            for (int e = 0; e < 4; e++) acc[mi][ni][e] = 0.f;

    int nk = K >> 5;   // BK = 32 halves

    #pragma unroll
    for (int s = 0; s < 3; s++) {
        uint32_t abase = sb + (uint32_t)s * STAGE_B;
        uint32_t bbase = abase + TILE_H * 2;
        const __half* Ag = Ap + s * 32;
        const __half* Bg = Bp + s * 32;
        #pragma unroll
        for (int u = 0; u < 2; u++) {
            cp_async16(abase + (uint32_t)(lr[u] * 80 + lc[u] * 16), Ag + (size_t)lr[u] * K + lc[u] * 8);
            cp_async16(bbase + (uint32_t)(lr[u] * 80 + lc[u] * 16), Bg + (size_t)lr[u] * K + lc[u] * 8);
        }
        cp_commit();
    }

    #pragma unroll 1
    for (int kt = 0; kt < nk; kt++) {
        cp_wait<2>();
        __syncthreads();

        if (kt + 3 < nk) {
            int s = (kt + 3) & 3;
            uint32_t abase = sb + (uint32_t)s * STAGE_B;
            uint32_t bbase = abase + TILE_H * 2;
            const __half* Ag = Ap + (kt + 3) * 32;
            const __half* Bg = Bp + (kt + 3) * 32;
            #pragma unroll
            for (int u = 0; u < 2; u++) {
                cp_async16(abase + (uint32_t)(lr[u] * 80 + lc[u] * 16), Ag + (size_t)lr[u] * K + lc[u] * 8);
                cp_async16(bbase + (uint32_t)(lr[u] * 80 + lc[u] * 16), Bg + (size_t)lr[u] * K + lc[u] * 8);
            }
        }
        cp_commit();

        const __half* As = smh + (size_t)(kt & 3) * 2 * TILE_H;
        const __half* Bs = As + TILE_H;
        #pragma unroll
        for (int ks = 0; ks < 2; ks++) {
            int k0 = ks * 16 + 2 * kq;
            uint32_t af[4][4];
            #pragma unroll
            for (int mi = 0; mi < 4; mi++) {
                const __half* ap = As + (wm * 64 + mi * 16 + g) * PADH;
                af[mi][0] = *(const uint32_t*)(ap + k0);
                af[mi][1] = *(const uint32_t*)(ap + 8 * PADH + k0);
                af[mi][2] = *(const uint32_t*)(ap + k0 + 8);
                af[mi][3] = *(const uint32_t*)(ap + 8 * PADH + k0 + 8);
            }
            uint32_t bf[4][2];
            #pragma unroll
            for (int ni = 0; ni < 4; ni++) {
                const __half* bp = Bs + (wn * 32 + ni * 8 + g) * PADH;
                bf[ni][0] = *(const uint32_t*)(bp + k0);
                bf[ni][1] = *(const uint32_t*)(bp + k0 + 8);
            }
            #pragma unroll
            for (int mi = 0; mi < 4; mi++)
                #pragma unroll
                for (int ni = 0; ni < 4; ni++)
                    mma_f16(acc[mi][ni], af[mi][0], af[mi][1], af[mi][2], af[mi][3],
                            bf[ni][0], bf[ni][1]);
        }
    }

    // epilogue
    #pragma unroll
    for (int mi = 0; mi < 4; mi++) {
        #pragma unroll
        for (int ni = 0; ni < 4; ni++) {
            int row = brow + wm * 64 + mi * 16 + g;
            int col = bcol + wn * 32 + ni * 8 + 2 * kq;
            #pragma unroll
            for (int half_ = 0; half_ < 2; half_++) {
                int r = row + half_ * 8;
                float v0 = acc[mi][ni][half_ * 2 + 0] + bias[col];
                float v1 = acc[mi][ni][half_ * 2 + 1] + bias[col + 1];
                if (mode == 1) {
                    v0 += res[(size_t)r * N + col];
                    v1 += res[(size_t)r * N + col + 1];
                    float2 o2 = { v0, v1 };
                    *(float2*)((float*)Cv + (size_t)r * N + col) = o2;
                } else {
                    if (mode == 2) {
                        float x0 = v0, x1 = v1;
                        v0 = 0.5f * x0 * (1.f + tanhf(0.7978845608028654f *
                                                      (x0 + 0.044715f * x0 * x0 * x0)));
                        v1 = 0.5f * x1 * (1.f + tanhf(0.7978845608028654f *
                                                      (x1 + 0.044715f * x1 * x1 * x1)));
                    }
                    *(uint32_t*)((__half*)Cv + (size_t)r * N + col) = pack_h2(v0, v1);
                }
            }
        }
    }
}

// ================= Causal flash attention, mma.sync fp16 =================
// QKV half [tok][3072], q pre-scaled by 1/8. CTA: 128 queries, key tiles 64.
#define APADH 72
#define ATTN_SMEM ((128+64+64)*APADH*2)

__global__ __launch_bounds__(256)
void attn_mma(const __half* __restrict__ QKV, __half* __restrict__ O)
{
    extern __shared__ __half smA[];
    __half* QP = smA;                    // 128 x APADH (Q staging, then P)
    __half* Ks = smA + 128 * APADH;      // 64 x APADH  [key][d]
    __half* Vt = Ks + 64 * APADH;        // 64 x APADH  [d][key]

    int tid = threadIdx.x, lane = tid & 31, w = tid >> 5;
    int g = lane >> 2, kq = lane & 3;
    int qb = blockIdx.x, h = blockIdx.y, b = blockIdx.z;
    size_t base  = ((size_t)b * SEQ) * QKVN + h * HDIM;
    size_t obase = ((size_t)b * SEQ) * EMB + h * HDIM;
    int wrow = w * 16;

    // stage Q tile 128x64 halves (already scaled)
    #pragma unroll
    for (int u = 0; u < 4; u++) {
        int idx = tid + u * 256;              // 0..1023
        int r = idx >> 3, c8 = (idx & 7) * 8;
        *(uint4*)(QP + r * APADH + c8) =
            *(const uint4*)(QKV + base + (size_t)(qb * 128 + r) * QKVN + c8);
    }
    __syncthreads();

    // Q fragments (16 rows x 64 d per warp): 4 k16-chunks
    uint32_t qa[4][4];
    #pragma unroll
    for (int ks = 0; ks < 4; ks++) {
        int k0 = ks * 16 + 2 * kq;
        qa[ks][0] = *(const uint32_t*)(QP + (wrow + g)     * APADH + k0);
        qa[ks][1] = *(const uint32_t*)(QP + (wrow + g + 8) * APADH + k0);
        qa[ks][2] = *(const uint32_t*)(QP + (wrow + g)     * APADH + k0 + 8);
        qa[ks][3] = *(const uint32_t*)(QP + (wrow + g + 8) * APADH + k0 + 8);
    }

    float m0 = -1e30f, m1 = -1e30f, l0 = 0.f, l1 = 0.f;
    float o[8][4];
    #pragma unroll
    for (int ni = 0; ni < 8; ni++)
        #pragma unroll
        for (int e = 0; e < 4; e++) o[ni][e] = 0.f;

    int nkt = 2 * qb + 2;
    #pragma unroll 1
    for (int kb = 0; kb < nkt; kb++) {
        __syncthreads();
        // K tile 64x64 halves
        #pragma unroll
        for (int u = 0; u < 2; u++) {
            int idx = tid + u * 256;          // 0..511
            int r = idx >> 3, c8 = (idx & 7) * 8;
            *(uint4*)(Ks + r * APADH + c8) =
                *(const uint4*)(QKV + base + EMB + (size_t)(kb * 64 + r) * QKVN + c8);
        }
        // V transposed: warp w -> d rows 8w..8w+7; lane covers key pair (2l,2l+1)
        {
            int l = lane;
            const __half* vsrc = QKV + base + 2 * EMB + (size_t)(kb * 64) * QKVN + w * 8;
            uint4 v0 = *(const uint4*)(vsrc + (size_t)(2 * l)     * QKVN);
            uint4 v1 = *(const uint4*)(vsrc + (size_t)(2 * l + 1) * QKVN);
            const uint16_t* p0 = reinterpret_cast<const uint16_t*>(&v0);
            const uint16_t* p1 = reinterpret_cast<const uint16_t*>(&v1);
            #pragma unroll
            for (int j = 0; j < 8; j++) {
                uint32_t pair = (uint32_t)p0[j] | ((uint32_t)p1[j] << 16);
                *(uint32_t*)(Vt + (w * 8 + j) * APADH + 2 * l) = pair;
            }
        }
        __syncthreads();

        // S = Q K^T
        float s[8][4];
        #pragma unroll
        for (int ni = 0; ni < 8; ni++)
            #pragma unroll
            for (int e = 0; e < 4; e++) s[ni][e] = 0.f;
        #pragma unroll
        for (int ks = 0; ks < 4; ks++) {
            int k0 = ks * 16 + 2 * kq;
            #pragma unroll
            for (int ni = 0; ni < 8; ni++) {
                uint32_t b0 = *(const uint32_t*)(Ks + (ni * 8 + g) * APADH + k0);
                uint32_t b1 = *(const uint32_t*)(Ks + (ni * 8 + g) * APADH + k0 + 8);
                mma_f16(s[ni], qa[ks][0], qa[ks][1], qa[ks][2], qa[ks][3], b0, b1);
            }
        }

        if (kb >= 2 * qb) {
            int row0 = qb * 128 + wrow + g;
            int row1 = row0 + 8;
            #pragma unroll
            for (int ni = 0; ni < 8; ni++) {
                int col = kb * 64 + ni * 8 + 2 * kq;
                if (col     > row0) s[ni][0] = -1e30f;
                if (col + 1 > row0) s[ni][1] = -1e30f;
                if (col     > row1) s[ni][2] = -1e30f;
                if (col + 1 > row1) s[ni][3] = -1e30f;
            }
        }

        float rm0 = -1e30f, rm1 = -1e30f;
        #pragma unroll
        for (int ni = 0; ni < 8; ni++) {
            rm0 = fmaxf(rm0, fmaxf(s[ni][0], s[ni][1]));
            rm1 = fmaxf(rm1, fmaxf(s[ni][2], s[ni][3]));
        }
        rm0 = fmaxf(rm0, __shfl_xor_sync(0xffffffffu, rm0, 1));
        rm0 = fmaxf(rm0, __shfl_xor_sync(0xffffffffu, rm0, 2));
        rm1 = fmaxf(rm1, __shfl_xor_sync(0xffffffffu, rm1, 1));
        rm1 = fmaxf(rm1, __shfl_xor_sync(0xffffffffu, rm1, 2));
        float mn0 = fmaxf(m0, rm0), mn1 = fmaxf(m1, rm1);
        float a0 = __expf(m0 - mn0), a1 = __expf(m1 - mn1);
        float rs0 = 0.f, rs1 = 0.f;
        #pragma unroll
        for (int ni = 0; ni < 8; ni++) {
            float p0 = __expf(s[ni][0] - mn0);
            float p1 = __expf(s[ni][1] - mn0);
            float p2 = __expf(s[ni][2] - mn1);
            float p3 = __expf(s[ni][3] - mn1);
            rs0 += p0 + p1; rs1 += p2 + p3;
            int col = ni * 8 + 2 * kq;
            *(uint32_t*)(QP + (wrow + g)     * APADH + col) = pack_h2(p0, p1);
            *(uint32_t*)(QP + (wrow + g + 8) * APADH + col) = pack_h2(p2, p3);
        }
        rs0 += __shfl_xor_sync(0xffffffffu, rs0, 1);
        rs0 += __shfl_xor_sync(0xffffffffu, rs0, 2);
        rs1 += __shfl_xor_sync(0xffffffffu, rs1, 1);
        rs1 += __shfl_xor_sync(0xffffffffu, rs1, 2);
        l0 = l0 * a0 + rs0;
        l1 = l1 * a1 + rs1;
        m0 = mn0; m1 = mn1;
        #pragma unroll
        for (int ni = 0; ni < 8; ni++) {
            o[ni][0] *= a0; o[ni][1] *= a0;
            o[ni][2] *= a1; o[ni][3] *= a1;
        }
        __syncwarp();

        // ctx += P @ V
        #pragma unroll
        for (int ks2 = 0; ks2 < 4; ks2++) {
            int k0 = ks2 * 16 + 2 * kq;
            uint32_t pa0 = *(const uint32_t*)(QP + (wrow + g)     * APADH + k0);
            uint32_t pa1 = *(const uint32_t*)(QP + (wrow + g + 8) * APADH + k0);
            uint32_t pa2 = *(const uint32_t*)(QP + (wrow + g)     * APADH + k0 + 8);
            uint32_t pa3 = *(const uint32_t*)(QP + (wrow + g + 8) * APADH + k0 + 8);
            #pragma unroll
            for (int ni = 0; ni < 8; ni++) {
                uint32_t b0 = *(const uint32_t*)(Vt + (ni * 8 + g) * APADH + k0);
                uint32_t b1 = *(const uint32_t*)(Vt + (ni * 8 + g) * APADH + k0 + 8);
                mma_f16(o[ni], pa0, pa1, pa2, pa3, b0, b1);
            }
        }
    }

    float inv0 = 1.0f / l0, inv1 = 1.0f / l1;
    size_t row0 = obase + (size_t)(qb * 128 + wrow + g) * EMB;
    size_t row1 = row0 + (size_t)8 * EMB;
    #pragma unroll
    for (int ni = 0; ni < 8; ni++) {
        int col = ni * 8 + 2 * kq;
        *(uint32_t*)(O + row0 + col) = pack_h2(o[ni][0] * inv0, o[ni][1] * inv0);
        *(uint32_t*)(O + row1 + col) = pack_h2(o[ni][2] * inv1, o[ni][3] * inv1);
    }
}

// ================= launch =================
extern "C" void kernel_launch(void* const* d_in, const int* in_sizes, int n_in,
                              void* d_out, int out_size)
{
    const float* x         = (const float*)d_in[0];
    const float* Wq        = (const float*)d_in[1];
    const float* bq        = (const float*)d_in[2];
    const float* Wk        = (const float*)d_in[3];
    const float* bk        = (const float*)d_in[4];
    const float* Wv        = (const float*)d_in[5];
    const float* bv        = (const float*)d_in[6];
    const float* Wo        = (const float*)d_in[7];
    const float* bo        = (const float*)d_in[8];
    const float* W1        = (const float*)d_in[9];
    const float* b1        = (const float*)d_in[10];
    const float* W2        = (const float*)d_in[11];
    const float* b2        = (const float*)d_in[12];
    const float* ln1_scale = (const float*)d_in[13];
    const float* ln1_shift = (const float*)d_in[14];
    const float* ln2_scale = (const float*)d_in[15];
    const float* ln2_shift = (const float*)d_in[16];
    float* out = (float*)d_out;

    __half *h, *qkv, *ctx, *ff, *wtqkv, *wto, *wt1, *wt2;
    float *x2, *bqkv;
    cudaGetSymbolAddress((void**)&h,     g_h);
    cudaGetSymbolAddress((void**)&qkv,   g_qkv);
    cudaGetSymbolAddress((void**)&ctx,   g_ctx);
    cudaGetSymbolAddress((void**)&x2,    g_x2);
    cudaGetSymbolAddress((void**)&ff,    g_ff);
    cudaGetSymbolAddress((void**)&bqkv,  g_bqkv);
    cudaGetSymbolAddress((void**)&wtqkv, g_wtqkv);
    cudaGetSymbolAddress((void**)&wto,   g_wto);
    cudaGetSymbolAddress((void**)&wt1,   g_wt1);
    cudaGetSymbolAddress((void**)&wt2,   g_wt2);

    cudaFuncSetAttribute(tc_gemm,  cudaFuncAttributeMaxDynamicSharedMemorySize, GEMM_SMEM);
    cudaFuncSetAttribute(attn_mma, cudaFuncAttributeMaxDynamicSharedMemorySize, ATTN_SMEM);

    dim3 tb(32, 8);
    dim3 gQKV(QKVN / 128, MTOT / 128);
    dim3 gE  (EMB  / 128, MTOT / 128);
    dim3 gF  (FF   / 128, MTOT / 128);
    dim3 gA  (SEQ / 128, NHEADS, BATCH);

    // weight prep (q-scale folded into Wq/bq)
    transpose_half<<<dim3(EMB/32, EMB/32), tb>>>(Wq, wtqkv,                     EMB, EMB, 0.125f);
    transpose_half<<<dim3(EMB/32, EMB/32), tb>>>(Wk, wtqkv + (size_t)EMB*EMB,   EMB, EMB, 1.0f);
    transpose_half<<<dim3(EMB/32, EMB/32), tb>>>(Wv, wtqkv + (size_t)2*EMB*EMB, EMB, EMB, 1.0f);
    transpose_half<<<dim3(EMB/32, EMB/32), tb>>>(Wo, wto, EMB, EMB, 1.0f);
    transpose_half<<<dim3(FF/32,  EMB/32), tb>>>(W1, wt1, EMB, FF, 1.0f);
    transpose_half<<<dim3(EMB/32, FF/32),  tb>>>(W2, wt2, FF, EMB, 1.0f);
    concat_bias<<<(QKVN + 255)/256, 256>>>(bq, bk, bv, bqkv);

    ln_kernel<<<MTOT, 256>>>(x, ln1_scale, ln1_shift, h);
    tc_gemm<<<gQKV, 256, GEMM_SMEM>>>(h, wtqkv, bqkv, nullptr, qkv, MTOT, QKVN, EMB, 0);
    attn_mma<<<gA, 256, ATTN_SMEM>>>(qkv, ctx);
    tc_gemm<<<gE, 256, GEMM_SMEM>>>(ctx, wto, bo, x, x2, MTOT, EMB, EMB, 1);
    ln_kernel<<<MTOT, 256>>>(x2, ln2_scale, ln2_shift, h);
    tc_gemm<<<gF, 256, GEMM_SMEM>>>(h, wt1, b1, nullptr, ff, MTOT, FF, EMB, 2);
    tc_gemm<<<gE, 256, GEMM_SMEM>>>(ff, wt2, b2, x2, out, MTOT, EMB, FF, 1);
}

// round 8
// speedup vs baseline: 2.0331x; 1.1068x over previous
#include <cuda_runtime.h>
#include <cuda_fp16.h>
#include <math.h>
#include <stdint.h>

#define BATCH 2
#define SEQ   2048
#define EMB   1024
#define NHEADS 16
#define HDIM  64
#define FF    4096
#define MTOT  (BATCH*SEQ)   /* 4096 rows */
#define QKVN  (3*EMB)       /* 3072 */

__device__ __forceinline__ uint32_t smem_u32(const void* p) {
    uint32_t a;
    asm("{ .reg .u64 t; cvta.to.shared.u64 t, %1; cvt.u32.u64 %0, t; }" : "=r"(a) : "l"(p));
    return a;
}
__device__ __forceinline__ void mma_f16(float c[4],
    uint32_t a0, uint32_t a1, uint32_t a2, uint32_t a3,
    uint32_t b0, uint32_t b1)
{
    asm volatile("mma.sync.aligned.m16n8k16.row.col.f32.f16.f16.f32 "
        "{%0,%1,%2,%3}, {%4,%5,%6,%7}, {%8,%9}, {%0,%1,%2,%3};"
        : "+f"(c[0]), "+f"(c[1]), "+f"(c[2]), "+f"(c[3])
        : "r"(a0), "r"(a1), "r"(a2), "r"(a3), "r"(b0), "r"(b1));
}
__device__ __forceinline__ void ldm_x4(uint32_t r[4], uint32_t saddr) {
    asm volatile("ldmatrix.sync.aligned.m8n8.x4.shared.b16 {%0,%1,%2,%3}, [%4];"
        : "=r"(r[0]), "=r"(r[1]), "=r"(r[2]), "=r"(r[3]) : "r"(saddr));
}
__device__ __forceinline__ void cp_async16(uint32_t saddr, const void* gptr) {
    asm volatile("cp.async.cg.shared.global [%0], [%1], 16;" :: "r"(saddr), "l"(gptr));
}
__device__ __forceinline__ void cp_commit() { asm volatile("cp.async.commit_group;" ::: "memory"); }
template<int N> __device__ __forceinline__ void cp_wait() {
    asm volatile("cp.async.wait_group %0;" :: "n"(N) : "memory");
}
__device__ __forceinline__ uint32_t pack_h2(float a, float b) {
    __half2 h = __floats2half2_rn(a, b);
    return *reinterpret_cast<uint32_t*>(&h);
}

// ================= scratch (device globals) =================
__device__ __half g_h  [MTOT*EMB];
__device__ __half g_qkv[(size_t)MTOT*QKVN];
__device__ __half g_ctx[MTOT*EMB];
__device__ float  g_x2 [MTOT*EMB];
__device__ __half g_ff [(size_t)MTOT*FF];
__device__ __half g_wtqkv[(size_t)QKVN*EMB];
__device__ __half g_wto[EMB*EMB];
__device__ __half g_wt1[(size_t)FF*EMB];
__device__ __half g_wt2[(size_t)EMB*FF];
__device__ float  g_bqkv[QKVN];

// ================= LayerNorm (ddof=1), half output =================
__global__ __launch_bounds__(256)
void ln_kernel(const float* __restrict__ x, const float* __restrict__ sc,
               const float* __restrict__ sh, __half* __restrict__ out)
{
    int row = blockIdx.x;
    const float* xr = x + (size_t)row * EMB;
    int t = threadIdx.x;
    float4 v4 = *(const float4*)(xr + t * 4);
    float v[4] = {v4.x, v4.y, v4.z, v4.w};
    __shared__ float red[8];
    float s = v[0] + v[1] + v[2] + v[3];
    #pragma unroll
    for (int o = 16; o; o >>= 1) s += __shfl_xor_sync(0xffffffffu, s, o);
    if ((t & 31) == 0) red[t >> 5] = s;
    __syncthreads();
    float tot = 0.f;
    #pragma unroll
    for (int i = 0; i < 8; i++) tot += red[i];
    float mean = tot * (1.0f / EMB);
    __syncthreads();
    float sq = 0.f;
    #pragma unroll
    for (int i = 0; i < 4; i++) { float d = v[i] - mean; sq += d * d; }
    #pragma unroll
    for (int o = 16; o; o >>= 1) sq += __shfl_xor_sync(0xffffffffu, sq, o);
    if ((t & 31) == 0) red[t >> 5] = sq;
    __syncthreads();
    float sqt = 0.f;
    #pragma unroll
    for (int i = 0; i < 8; i++) sqt += red[i];
    float rstd = rsqrtf(sqt * (1.0f / (EMB - 1)) + 1e-5f);
    float r[4];
    #pragma unroll
    for (int i = 0; i < 4; i++) {
        int c = t * 4 + i;
        r[i] = sc[c] * (v[i] - mean) * rstd + sh[c];
    }
    uint2 st = { pack_h2(r[0], r[1]), pack_h2(r[2], r[3]) };
    *(uint2*)(out + (size_t)row * EMB + t * 4) = st;
}

// ================= fused weight prep: all transposes + bias concat =================
// grid.x = 12300, block = (32,8). Tiles: [0,3072)=Wq|Wk|Wv, [3072,4096)=Wo,
// [4096,8192)=W1, [8192,12288)=W2, [12288,12300)=bias.
__global__ __launch_bounds__(256)
void prep_weights(const float* __restrict__ Wq, const float* __restrict__ Wk,
                  const float* __restrict__ Wv, const float* __restrict__ Wo,
                  const float* __restrict__ W1, const float* __restrict__ W2,
                  const float* __restrict__ bq, const float* __restrict__ bk,
                  const float* __restrict__ bv,
                  __half* __restrict__ wtqkv, __half* __restrict__ wto,
                  __half* __restrict__ wt1, __half* __restrict__ wt2,
                  float* __restrict__ bqkv)
{
    int bid = blockIdx.x;
    int tx = threadIdx.x, ty = threadIdx.y;
    if (bid >= 12288) {
        int i = (bid - 12288) * 256 + ty * 32 + tx;
        if (i < EMB)            bqkv[i] = bq[i] * 0.125f;   // fold 1/sqrt(HDIM)
        else if (i < 2 * EMB)   bqkv[i] = bk[i - EMB];
        else if (i < 3 * EMB)   bqkv[i] = bv[i - 2 * EMB];
        return;
    }
    const float* W; __half* Wt; int K, N, tiles_x, t; float scale = 1.f;
    if (bid < 3072) {
        int w = bid >> 10; t = bid & 1023;
        W = (w == 0) ? Wq : (w == 1) ? Wk : Wv;
        Wt = wtqkv + (size_t)w * EMB * EMB;
        K = EMB; N = EMB; tiles_x = 32;
        if (w == 0) scale = 0.125f;
    } else if (bid < 4096) {
        t = bid - 3072; W = Wo; Wt = wto; K = EMB; N = EMB; tiles_x = 32;
    } else if (bid < 8192) {
        t = bid - 4096; W = W1; Wt = wt1; K = EMB; N = FF; tiles_x = 128;
    } else {
        t = bid - 8192; W = W2; Wt = wt2; K = FF; N = EMB; tiles_x = 32;
    }
    int x0 = (t % tiles_x) * 32, y0 = (t / tiles_x) * 32;
    __shared__ float tile[32][33];
    #pragma unroll
    for (int j = 0; j < 32; j += 8)
        tile[ty + j][tx] = W[(size_t)(y0 + ty + j) * N + x0 + tx];
    __syncthreads();
    #pragma unroll
    for (int j = 0; j < 32; j += 8)
        Wt[(size_t)(x0 + ty + j) * K + y0 + tx] = __float2half(tile[tx][ty + j] * scale);
}

// ================= fp16 mma.sync GEMM, 4-stage cp.async + ldmatrix =================
// C[M,N] = A[M,K] @ Wt[N,K]^T + bias (+res | gelu). CTA 128x128, BK=32 halves.
// 8 warps (2M x 4N), warp tile 64x32.
#define PADH 40                              /* halves per SMEM row (80B) */
#define TILE_H (128*PADH)
#define STAGE_B (2*TILE_H*2)                 /* 20480 bytes */
#define GEMM_SMEM (4*STAGE_B)                /* 81920 */

__global__ __launch_bounds__(256, 2)
void tc_gemm(const __half* __restrict__ A, const __half* __restrict__ Bt,
             const float* __restrict__ bias, const float* __restrict__ res,
             void* __restrict__ Cv, int M, int N, int K, int mode)
{
    extern __shared__ __half smh[];
    uint32_t sb = smem_u32(smh);

    int tid  = threadIdx.x;
    int lane = tid & 31, wid = tid >> 5;
    int g    = lane >> 2;
    int kq   = lane & 3;
    int wm   = wid & 1;
    int wn   = wid >> 1;
    int bcol = blockIdx.x * 128, brow = blockIdx.y * 128;

    // ldmatrix per-thread address components
    int a_r  = (lane & 7) + ((lane >> 3) & 1) * 8;
    int a_k8 = (lane >> 4) * 8;
    int b_r  = (lane & 7) + (lane >> 4) * 8;
    int b_k8 = ((lane >> 3) & 1) * 8;

    const __half* Ap = A  + (size_t)brow * K;
    const __half* Bp = Bt + (size_t)bcol * K;

    int lr[2], lc[2];
    #pragma unroll
    for (int u = 0; u < 2; u++) {
        int idx = tid + u * 256;
        lr[u] = idx >> 2;
        lc[u] = idx & 3;
    }

    float acc[4][4][4];
    #pragma unroll
    for (int mi = 0; mi < 4; mi++)
        #pragma unroll
        for (int ni = 0; ni < 4; ni++)
            #pragma unroll
            for (int e = 0; e < 4; e++) acc[mi][ni][e] = 0.f;

    int nk = K >> 5;

    #pragma unroll
    for (int s = 0; s < 3; s++) {
        uint32_t abase = sb + (uint32_t)s * STAGE_B;
        uint32_t bbase = abase + TILE_H * 2;
        const __half* Ag = Ap + s * 32;
        const __half* Bg = Bp + s * 32;
        #pragma unroll
        for (int u = 0; u < 2; u++) {
            cp_async16(abase + (uint32_t)(lr[u] * 80 + lc[u] * 16), Ag + (size_t)lr[u] * K + lc[u] * 8);
            cp_async16(bbase + (uint32_t)(lr[u] * 80 + lc[u] * 16), Bg + (size_t)lr[u] * K + lc[u] * 8);
        }
        cp_commit();
    }

    #pragma unroll 1
    for (int kt = 0; kt < nk; kt++) {
        cp_wait<2>();
        __syncthreads();

        if (kt + 3 < nk) {
            int s = (kt + 3) & 3;
            uint32_t abase = sb + (uint32_t)s * STAGE_B;
            uint32_t bbase = abase + TILE_H * 2;
            const __half* Ag = Ap + (kt + 3) * 32;
            const __half* Bg = Bp + (kt + 3) * 32;
            #pragma unroll
            for (int u = 0; u < 2; u++) {
                cp_async16(abase + (uint32_t)(lr[u] * 80 + lc[u] * 16), Ag + (size_t)lr[u] * K + lc[u] * 8);
                cp_async16(bbase + (uint32_t)(lr[u] * 80 + lc[u] * 16), Bg + (size_t)lr[u] * K + lc[u] * 8);
            }
        }
        cp_commit();

        uint32_t As_b = sb + (uint32_t)(kt & 3) * STAGE_B;
        uint32_t Bs_b = As_b + TILE_H * 2;
        #pragma unroll
        for (int ks = 0; ks < 2; ks++) {
            int k0 = ks * 16;
            uint32_t af[4][4], bf[4][2];
            #pragma unroll
            for (int mi = 0; mi < 4; mi++)
                ldm_x4(af[mi], As_b + (uint32_t)((wm * 64 + mi * 16 + a_r) * PADH + k0 + a_k8) * 2);
            #pragma unroll
            for (int nj = 0; nj < 2; nj++)
                ldm_x4(&bf[2 * nj][0], Bs_b + (uint32_t)((wn * 32 + nj * 16 + b_r) * PADH + k0 + b_k8) * 2);
            #pragma unroll
            for (int mi = 0; mi < 4; mi++)
                #pragma unroll
                for (int ni = 0; ni < 4; ni++)
                    mma_f16(acc[mi][ni], af[mi][0], af[mi][1], af[mi][2], af[mi][3],
                            bf[ni][0], bf[ni][1]);
        }
    }

    // epilogue
    #pragma unroll
    for (int mi = 0; mi < 4; mi++) {
        #pragma unroll
        for (int ni = 0; ni < 4; ni++) {
            int row = brow + wm * 64 + mi * 16 + g;
            int col = bcol + wn * 32 + ni * 8 + 2 * kq;
            #pragma unroll
            for (int half_ = 0; half_ < 2; half_++) {
                int r = row + half_ * 8;
                float v0 = acc[mi][ni][half_ * 2 + 0] + bias[col];
                float v1 = acc[mi][ni][half_ * 2 + 1] + bias[col + 1];
                if (mode == 1) {
                    v0 += res[(size_t)r * N + col];
                    v1 += res[(size_t)r * N + col + 1];
                    float2 o2 = { v0, v1 };
                    *(float2*)((float*)Cv + (size_t)r * N + col) = o2;
                } else {
                    if (mode == 2) {
                        float x0 = v0, x1 = v1;
                        v0 = 0.5f * x0 * (1.f + tanhf(0.7978845608028654f *
                                                      (x0 + 0.044715f * x0 * x0 * x0)));
                        v1 = 0.5f * x1 * (1.f + tanhf(0.7978845608028654f *
                                                      (x1 + 0.044715f * x1 * x1 * x1)));
                    }
                    *(uint32_t*)((__half*)Cv + (size_t)r * N + col) = pack_h2(v0, v1);
                }
            }
        }
    }
}

// ================= Causal flash attention, mma.sync fp16 + ldmatrix =================
#define APADH 72
#define ATTN_SMEM ((128+64+64)*APADH*2)

__global__ __launch_bounds__(256)
void attn_mma(const __half* __restrict__ QKV, __half* __restrict__ O)
{
    extern __shared__ __half smA[];
    __half* QP = smA;                    // 128 x APADH (Q staging, then P)
    __half* Ks = smA + 128 * APADH;      // 64 x APADH  [key][d]
    __half* Vt = Ks + 64 * APADH;        // 64 x APADH  [d][key]
    uint32_t qp_b = smem_u32(QP);
    uint32_t ks_b = smem_u32(Ks);
    uint32_t vt_b = smem_u32(Vt);

    int tid = threadIdx.x, lane = tid & 31, w = tid >> 5;
    int g = lane >> 2, kq = lane & 3;
    int qb = gridDim.x - 1 - blockIdx.x;   // heavy causal tiles first
    int h = blockIdx.y, b = blockIdx.z;
    size_t base  = ((size_t)b * SEQ) * QKVN + h * HDIM;
    size_t obase = ((size_t)b * SEQ) * EMB + h * HDIM;
    int wrow = w * 16;

    int a_r  = (lane & 7) + ((lane >> 3) & 1) * 8;
    int a_k8 = (lane >> 4) * 8;
    int b_r  = (lane & 7) + (lane >> 4) * 8;
    int b_k8 = ((lane >> 3) & 1) * 8;

    // stage Q tile 128x64 halves (already scaled)
    #pragma unroll
    for (int u = 0; u < 4; u++) {
        int idx = tid + u * 256;
        int r = idx >> 3, c8 = (idx & 7) * 8;
        *(uint4*)(QP + r * APADH + c8) =
            *(const uint4*)(QKV + base + (size_t)(qb * 128 + r) * QKVN + c8);
    }
    __syncthreads();

    uint32_t qa[4][4];
    #pragma unroll
    for (int ks = 0; ks < 4; ks++)
        ldm_x4(qa[ks], qp_b + (uint32_t)((wrow + a_r) * APADH + ks * 16 + a_k8) * 2);

    float m0 = -1e30f, m1 = -1e30f, l0 = 0.f, l1 = 0.f;
    float o[8][4];
    #pragma unroll
    for (int ni = 0; ni < 8; ni++)
        #pragma unroll
        for (int e = 0; e < 4; e++) o[ni][e] = 0.f;

    int nkt = 2 * qb + 2;
    #pragma unroll 1
    for (int kb = 0; kb < nkt; kb++) {
        __syncthreads();
        #pragma unroll
        for (int u = 0; u < 2; u++) {
            int idx = tid + u * 256;
            int r = idx >> 3, c8 = (idx & 7) * 8;
            *(uint4*)(Ks + r * APADH + c8) =
                *(const uint4*)(QKV + base + EMB + (size_t)(kb * 64 + r) * QKVN + c8);
        }
        {
            int l = lane;
            const __half* vsrc = QKV + base + 2 * EMB + (size_t)(kb * 64) * QKVN + w * 8;
            uint4 v0 = *(const uint4*)(vsrc + (size_t)(2 * l)     * QKVN);
            uint4 v1 = *(const uint4*)(vsrc + (size_t)(2 * l + 1) * QKVN);
            const uint16_t* p0 = reinterpret_cast<const uint16_t*>(&v0);
            const uint16_t* p1 = reinterpret_cast<const uint16_t*>(&v1);
            #pragma unroll
            for (int j = 0; j < 8; j++) {
                uint32_t pair = (uint32_t)p0[j] | ((uint32_t)p1[j] << 16);
                *(uint32_t*)(Vt + (w * 8 + j) * APADH + 2 * l) = pair;
            }
        }
        __syncthreads();

        // S = Q K^T
        float s[8][4];
        #pragma unroll
        for (int ni = 0; ni < 8; ni++)
            #pragma unroll
            for (int e = 0; e < 4; e++) s[ni][e] = 0.f;
        #pragma unroll
        for (int ks = 0; ks < 4; ks++) {
            #pragma unroll
            for (int nj = 0; nj < 4; nj++) {
                uint32_t bf[4];
                ldm_x4(bf, ks_b + (uint32_t)((nj * 16 + b_r) * APADH + ks * 16 + b_k8) * 2);
                mma_f16(s[2 * nj],     qa[ks][0], qa[ks][1], qa[ks][2], qa[ks][3], bf[0], bf[1]);
                mma_f16(s[2 * nj + 1], qa[ks][0], qa[ks][1], qa[ks][2], qa[ks][3], bf[2], bf[3]);
            }
        }

        if (kb >= 2 * qb) {
            int row0 = qb * 128 + wrow + g;
            int row1 = row0 + 8;
            #pragma unroll
            for (int ni = 0; ni < 8; ni++) {
                int col = kb * 64 + ni * 8 + 2 * kq;
                if (col     > row0) s[ni][0] = -1e30f;
                if (col + 1 > row0) s[ni][1] = -1e30f;
                if (col     > row1) s[ni][2] = -1e30f;
                if (col + 1 > row1) s[ni][3] = -1e30f;
            }
        }

        float rm0 = -1e30f, rm1 = -1e30f;
        #pragma unroll
        for (int ni = 0; ni < 8; ni++) {
            rm0 = fmaxf(rm0, fmaxf(s[ni][0], s[ni][1]));
            rm1 = fmaxf(rm1, fmaxf(s[ni][2], s[ni][3]));
        }
        rm0 = fmaxf(rm0, __shfl_xor_sync(0xffffffffu, rm0, 1));
        rm0 = fmaxf(rm0, __shfl_xor_sync(0xffffffffu, rm0, 2));
        rm1 = fmaxf(rm1, __shfl_xor_sync(0xffffffffu, rm1, 1));
        rm1 = fmaxf(rm1, __shfl_xor_sync(0xffffffffu, rm1, 2));
        float mn0 = fmaxf(m0, rm0), mn1 = fmaxf(m1, rm1);
        float a0 = __expf(m0 - mn0), a1 = __expf(m1 - mn1);
        float rs0 = 0.f, rs1 = 0.f;
        #pragma unroll
        for (int ni = 0; ni < 8; ni++) {
            float p0 = __expf(s[ni][0] - mn0);
            float p1 = __expf(s[ni][1] - mn0);
            float p2 = __expf(s[ni][2] - mn1);
            float p3 = __expf(s[ni][3] - mn1);
            rs0 += p0 + p1; rs1 += p2 + p3;
            int col = ni * 8 + 2 * kq;
            *(uint32_t*)(QP + (wrow + g)     * APADH + col) = pack_h2(p0, p1);
            *(uint32_t*)(QP + (wrow + g + 8) * APADH + col) = pack_h2(p2, p3);
        }
        rs0 += __shfl_xor_sync(0xffffffffu, rs0, 1);
        rs0 += __shfl_xor_sync(0xffffffffu, rs0, 2);
        rs1 += __shfl_xor_sync(0xffffffffu, rs1, 1);
        rs1 += __shfl_xor_sync(0xffffffffu, rs1, 2);
        l0 = l0 * a0 + rs0;
        l1 = l1 * a1 + rs1;
        m0 = mn0; m1 = mn1;
        #pragma unroll
        for (int ni = 0; ni < 8; ni++) {
            o[ni][0] *= a0; o[ni][1] *= a0;
            o[ni][2] *= a1; o[ni][3] *= a1;
        }
        __syncwarp();

        // ctx += P @ V
        #pragma unroll
        for (int ks2 = 0; ks2 < 4; ks2++) {
            uint32_t pa[4];
            ldm_x4(pa, qp_b + (uint32_t)((wrow + a_r) * APADH + ks2 * 16 + a_k8) * 2);
            #pragma unroll
            for (int nj = 0; nj < 4; nj++) {
                uint32_t bf[4];
                ldm_x4(bf, vt_b + (uint32_t)((nj * 16 + b_r) * APADH + ks2 * 16 + b_k8) * 2);
                mma_f16(o[2 * nj],     pa[0], pa[1], pa[2], pa[3], bf[0], bf[1]);
                mma_f16(o[2 * nj + 1], pa[0], pa[1], pa[2], pa[3], bf[2], bf[3]);
            }
        }
    }

    float inv0 = 1.0f / l0, inv1 = 1.0f / l1;
    size_t row0 = obase + (size_t)(qb * 128 + wrow + g) * EMB;
    size_t row1 = row0 + (size_t)8 * EMB;
    #pragma unroll
    for (int ni = 0; ni < 8; ni++) {
        int col = ni * 8 + 2 * kq;
        *(uint32_t*)(O + row0 + col) = pack_h2(o[ni][0] * inv0, o[ni][1] * inv0);
        *(uint32_t*)(O + row1 + col) = pack_h2(o[ni][2] * inv1, o[ni][3] * inv1);
    }
}

// ================= launch =================
extern "C" void kernel_launch(void* const* d_in, const int* in_sizes, int n_in,
                              void* d_out, int out_size)
{
    const float* x         = (const float*)d_in[0];
    const float* Wq        = (const float*)d_in[1];
    const float* bq        = (const float*)d_in[2];
    const float* Wk        = (const float*)d_in[3];
    const float* bk        = (const float*)d_in[4];
    const float* Wv        = (const float*)d_in[5];
    const float* bv        = (const float*)d_in[6];
    const float* Wo        = (const float*)d_in[7];
    const float* bo        = (const float*)d_in[8];
    const float* W1        = (const float*)d_in[9];
    const float* b1        = (const float*)d_in[10];
    const float* W2        = (const float*)d_in[11];
    const float* b2        = (const float*)d_in[12];
    const float* ln1_scale = (const float*)d_in[13];
    const float* ln1_shift = (const float*)d_in[14];
    const float* ln2_scale = (const float*)d_in[15];
    const float* ln2_shift = (const float*)d_in[16];
    float* out = (float*)d_out;

    __half *h, *qkv, *ctx, *ff, *wtqkv, *wto, *wt1, *wt2;
    float *x2, *bqkv;
    cudaGetSymbolAddress((void**)&h,     g_h);
    cudaGetSymbolAddress((void**)&qkv,   g_qkv);
    cudaGetSymbolAddress((void**)&ctx,   g_ctx);
    cudaGetSymbolAddress((void**)&x2,    g_x2);
    cudaGetSymbolAddress((void**)&ff,    g_ff);
    cudaGetSymbolAddress((void**)&bqkv,  g_bqkv);
    cudaGetSymbolAddress((void**)&wtqkv, g_wtqkv);
    cudaGetSymbolAddress((void**)&wto,   g_wto);
    cudaGetSymbolAddress((void**)&wt1,   g_wt1);
    cudaGetSymbolAddress((void**)&wt2,   g_wt2);

    cudaFuncSetAttribute(tc_gemm,  cudaFuncAttributeMaxDynamicSharedMemorySize, GEMM_SMEM);
    cudaFuncSetAttribute(attn_mma, cudaFuncAttributeMaxDynamicSharedMemorySize, ATTN_SMEM);

    dim3 gQKV(QKVN / 128, MTOT / 128);
    dim3 gE  (EMB  / 128, MTOT / 128);
    dim3 gF  (FF   / 128, MTOT / 128);
    dim3 gA  (SEQ / 128, NHEADS, BATCH);

    prep_weights<<<12300, dim3(32, 8)>>>(Wq, Wk, Wv, Wo, W1, W2, bq, bk, bv,
                                         wtqkv, wto, wt1, wt2, bqkv);
    ln_kernel<<<MTOT, 256>>>(x, ln1_scale, ln1_shift, h);
    tc_gemm<<<gQKV, 256, GEMM_SMEM>>>(h, wtqkv, bqkv, nullptr, qkv, MTOT, QKVN, EMB, 0);
    attn_mma<<<gA, 256, ATTN_SMEM>>>(qkv, ctx);
    tc_gemm<<<gE, 256, GEMM_SMEM>>>(ctx, wto, bo, x, x2, MTOT, EMB, EMB, 1);
    ln_kernel<<<MTOT, 256>>>(x2, ln2_scale, ln2_shift, h);
    tc_gemm<<<gF, 256, GEMM_SMEM>>>(h, wt1, b1, nullptr, ff, MTOT, FF, EMB, 2);
    tc_gemm<<<gE, 256, GEMM_SMEM>>>(ff, wt2, b2, x2, out, MTOT, EMB, FF, 1);
}

// round 9
// speedup vs baseline: 2.1276x; 1.0465x over previous
#include <cuda_runtime.h>
#include <cuda_fp16.h>
#include <math.h>
#include <stdint.h>

#define BATCH 2
#define SEQ   2048
#define EMB   1024
#define NHEADS 16
#define HDIM  64
#define FF    4096
#define MTOT  (BATCH*SEQ)   /* 4096 rows */
#define QKVN  (3*EMB)       /* 3072 */

__device__ __forceinline__ uint32_t smem_u32(const void* p) {
    uint32_t a;
    asm("{ .reg .u64 t; cvta.to.shared.u64 t, %1; cvt.u32.u64 %0, t; }" : "=r"(a) : "l"(p));
    return a;
}
__device__ __forceinline__ void mma_f16(float c[4],
    uint32_t a0, uint32_t a1, uint32_t a2, uint32_t a3,
    uint32_t b0, uint32_t b1)
{
    asm volatile("mma.sync.aligned.m16n8k16.row.col.f32.f16.f16.f32 "
        "{%0,%1,%2,%3}, {%4,%5,%6,%7}, {%8,%9}, {%0,%1,%2,%3};"
        : "+f"(c[0]), "+f"(c[1]), "+f"(c[2]), "+f"(c[3])
        : "r"(a0), "r"(a1), "r"(a2), "r"(a3), "r"(b0), "r"(b1));
}
__device__ __forceinline__ void ldm_x4(uint32_t r[4], uint32_t saddr) {
    asm volatile("ldmatrix.sync.aligned.m8n8.x4.shared.b16 {%0,%1,%2,%3}, [%4];"
        : "=r"(r[0]), "=r"(r[1]), "=r"(r[2]), "=r"(r[3]) : "r"(saddr));
}
__device__ __forceinline__ void ldm_x4_trans(uint32_t r[4], uint32_t saddr) {
    asm volatile("ldmatrix.sync.aligned.m8n8.x4.trans.shared.b16 {%0,%1,%2,%3}, [%4];"
        : "=r"(r[0]), "=r"(r[1]), "=r"(r[2]), "=r"(r[3]) : "r"(saddr));
}
__device__ __forceinline__ void cp_async16(uint32_t saddr, const void* gptr) {
    asm volatile("cp.async.cg.shared.global [%0], [%1], 16;" :: "r"(saddr), "l"(gptr));
}
__device__ __forceinline__ void cp_commit() { asm volatile("cp.async.commit_group;" ::: "memory"); }
template<int N> __device__ __forceinline__ void cp_wait() {
    asm volatile("cp.async.wait_group %0;" :: "n"(N) : "memory");
}
__device__ __forceinline__ uint32_t pack_h2(float a, float b) {
    __half2 h = __floats2half2_rn(a, b);
    return *reinterpret_cast<uint32_t*>(&h);
}

// ================= scratch (device globals) =================
__device__ __half g_h  [MTOT*EMB];
__device__ __half g_qkv[(size_t)MTOT*QKVN];
__device__ __half g_ctx[MTOT*EMB];
__device__ float  g_x2 [MTOT*EMB];
__device__ __half g_ff [(size_t)MTOT*FF];
__device__ __half g_wtqkv[(size_t)QKVN*EMB];
__device__ __half g_wto[EMB*EMB];
__device__ __half g_wt1[(size_t)FF*EMB];
__device__ __half g_wt2[(size_t)EMB*FF];
__device__ float  g_bqkv[QKVN];

// ================= LayerNorm (ddof=1), half output =================
__global__ __launch_bounds__(256)
void ln_kernel(const float* __restrict__ x, const float* __restrict__ sc,
               const float* __restrict__ sh, __half* __restrict__ out)
{
    int row = blockIdx.x;
    const float* xr = x + (size_t)row * EMB;
    int t = threadIdx.x;
    float4 v4 = *(const float4*)(xr + t * 4);
    float v[4] = {v4.x, v4.y, v4.z, v4.w};
    __shared__ float red[8];
    float s = v[0] + v[1] + v[2] + v[3];
    #pragma unroll
    for (int o = 16; o; o >>= 1) s += __shfl_xor_sync(0xffffffffu, s, o);
    if ((t & 31) == 0) red[t >> 5] = s;
    __syncthreads();
    float tot = 0.f;
    #pragma unroll
    for (int i = 0; i < 8; i++) tot += red[i];
    float mean = tot * (1.0f / EMB);
    __syncthreads();
    float sq = 0.f;
    #pragma unroll
    for (int i = 0; i < 4; i++) { float d = v[i] - mean; sq += d * d; }
    #pragma unroll
    for (int o = 16; o; o >>= 1) sq += __shfl_xor_sync(0xffffffffu, sq, o);
    if ((t & 31) == 0) red[t >> 5] = sq;
    __syncthreads();
    float sqt = 0.f;
    #pragma unroll
    for (int i = 0; i < 8; i++) sqt += red[i];
    float rstd = rsqrtf(sqt * (1.0f / (EMB - 1)) + 1e-5f);
    float r[4];
    #pragma unroll
    for (int i = 0; i < 4; i++) {
        int c = t * 4 + i;
        r[i] = sc[c] * (v[i] - mean) * rstd + sh[c];
    }
    uint2 st = { pack_h2(r[0], r[1]), pack_h2(r[2], r[3]) };
    *(uint2*)(out + (size_t)row * EMB + t * 4) = st;
}

// ================= fused weight prep =================
__global__ __launch_bounds__(256)
void prep_weights(const float* __restrict__ Wq, const float* __restrict__ Wk,
                  const float* __restrict__ Wv, const float* __restrict__ Wo,
                  const float* __restrict__ W1, const float* __restrict__ W2,
                  const float* __restrict__ bq, const float* __restrict__ bk,
                  const float* __restrict__ bv,
                  __half* __restrict__ wtqkv, __half* __restrict__ wto,
                  __half* __restrict__ wt1, __half* __restrict__ wt2,
                  float* __restrict__ bqkv)
{
    int bid = blockIdx.x;
    int tx = threadIdx.x, ty = threadIdx.y;
    if (bid >= 12288) {
        int i = (bid - 12288) * 256 + ty * 32 + tx;
        if (i < EMB)            bqkv[i] = bq[i] * 0.125f;
        else if (i < 2 * EMB)   bqkv[i] = bk[i - EMB];
        else if (i < 3 * EMB)   bqkv[i] = bv[i - 2 * EMB];
        return;
    }
    const float* W; __half* Wt; int K, N, tiles_x, t; float scale = 1.f;
    if (bid < 3072) {
        int w = bid >> 10; t = bid & 1023;
        W = (w == 0) ? Wq : (w == 1) ? Wk : Wv;
        Wt = wtqkv + (size_t)w * EMB * EMB;
        K = EMB; N = EMB; tiles_x = 32;
        if (w == 0) scale = 0.125f;
    } else if (bid < 4096) {
        t = bid - 3072; W = Wo; Wt = wto; K = EMB; N = EMB; tiles_x = 32;
    } else if (bid < 8192) {
        t = bid - 4096; W = W1; Wt = wt1; K = EMB; N = FF; tiles_x = 128;
    } else {
        t = bid - 8192; W = W2; Wt = wt2; K = FF; N = EMB; tiles_x = 32;
    }
    int x0 = (t % tiles_x) * 32, y0 = (t / tiles_x) * 32;
    __shared__ float tile[32][33];
    #pragma unroll
    for (int j = 0; j < 32; j += 8)
        tile[ty + j][tx] = W[(size_t)(y0 + ty + j) * N + x0 + tx];
    __syncthreads();
    #pragma unroll
    for (int j = 0; j < 32; j += 8)
        Wt[(size_t)(x0 + ty + j) * K + y0 + tx] = __float2half(tile[tx][ty + j] * scale);
}

// ================= fp16 mma.sync GEMM (unchanged from R8) =================
#define PADH 40
#define TILE_H (128*PADH)
#define STAGE_B (2*TILE_H*2)
#define GEMM_SMEM (4*STAGE_B)

__global__ __launch_bounds__(256, 2)
void tc_gemm(const __half* __restrict__ A, const __half* __restrict__ Bt,
             const float* __restrict__ bias, const float* __restrict__ res,
             void* __restrict__ Cv, int M, int N, int K, int mode)
{
    extern __shared__ __half smh[];
    uint32_t sb = smem_u32(smh);

    int tid  = threadIdx.x;
    int lane = tid & 31, wid = tid >> 5;
    int g    = lane >> 2;
    int kq   = lane & 3;
    int wm   = wid & 1;
    int wn   = wid >> 1;
    int bcol = blockIdx.x * 128, brow = blockIdx.y * 128;

    int a_r  = (lane & 7) + ((lane >> 3) & 1) * 8;
    int a_k8 = (lane >> 4) * 8;
    int b_r  = (lane & 7) + (lane >> 4) * 8;
    int b_k8 = ((lane >> 3) & 1) * 8;

    const __half* Ap = A  + (size_t)brow * K;
    const __half* Bp = Bt + (size_t)bcol * K;

    int lr[2], lc[2];
    #pragma unroll
    for (int u = 0; u < 2; u++) {
        int idx = tid + u * 256;
        lr[u] = idx >> 2;
        lc[u] = idx & 3;
    }

    float acc[4][4][4];
    #pragma unroll
    for (int mi = 0; mi < 4; mi++)
        #pragma unroll
        for (int ni = 0; ni < 4; ni++)
            #pragma unroll
            for (int e = 0; e < 4; e++) acc[mi][ni][e] = 0.f;

    int nk = K >> 5;

    #pragma unroll
    for (int s = 0; s < 3; s++) {
        uint32_t abase = sb + (uint32_t)s * STAGE_B;
        uint32_t bbase = abase + TILE_H * 2;
        const __half* Ag = Ap + s * 32;
        const __half* Bg = Bp + s * 32;
        #pragma unroll
        for (int u = 0; u < 2; u++) {
            cp_async16(abase + (uint32_t)(lr[u] * 80 + lc[u] * 16), Ag + (size_t)lr[u] * K + lc[u] * 8);
            cp_async16(bbase + (uint32_t)(lr[u] * 80 + lc[u] * 16), Bg + (size_t)lr[u] * K + lc[u] * 8);
        }
        cp_commit();
    }

    #pragma unroll 1
    for (int kt = 0; kt < nk; kt++) {
        cp_wait<2>();
        __syncthreads();

        if (kt + 3 < nk) {
            int s = (kt + 3) & 3;
            uint32_t abase = sb + (uint32_t)s * STAGE_B;
            uint32_t bbase = abase + TILE_H * 2;
            const __half* Ag = Ap + (kt + 3) * 32;
            const __half* Bg = Bp + (kt + 3) * 32;
            #pragma unroll
            for (int u = 0; u < 2; u++) {
                cp_async16(abase + (uint32_t)(lr[u] * 80 + lc[u] * 16), Ag + (size_t)lr[u] * K + lc[u] * 8);
                cp_async16(bbase + (uint32_t)(lr[u] * 80 + lc[u] * 16), Bg + (size_t)lr[u] * K + lc[u] * 8);
            }
        }
        cp_commit();

        uint32_t As_b = sb + (uint32_t)(kt & 3) * STAGE_B;
        uint32_t Bs_b = As_b + TILE_H * 2;
        #pragma unroll
        for (int ks = 0; ks < 2; ks++) {
            int k0 = ks * 16;
            uint32_t af[4][4], bf[4][2];
            #pragma unroll
            for (int mi = 0; mi < 4; mi++)
                ldm_x4(af[mi], As_b + (uint32_t)((wm * 64 + mi * 16 + a_r) * PADH + k0 + a_k8) * 2);
            #pragma unroll
            for (int nj = 0; nj < 2; nj++)
                ldm_x4(&bf[2 * nj][0], Bs_b + (uint32_t)((wn * 32 + nj * 16 + b_r) * PADH + k0 + b_k8) * 2);
            #pragma unroll
            for (int mi = 0; mi < 4; mi++)
                #pragma unroll
                for (int ni = 0; ni < 4; ni++)
                    mma_f16(acc[mi][ni], af[mi][0], af[mi][1], af[mi][2], af[mi][3],
                            bf[ni][0], bf[ni][1]);
        }
    }

    #pragma unroll
    for (int mi = 0; mi < 4; mi++) {
        #pragma unroll
        for (int ni = 0; ni < 4; ni++) {
            int row = brow + wm * 64 + mi * 16 + g;
            int col = bcol + wn * 32 + ni * 8 + 2 * kq;
            #pragma unroll
            for (int half_ = 0; half_ < 2; half_++) {
                int r = row + half_ * 8;
                float v0 = acc[mi][ni][half_ * 2 + 0] + bias[col];
                float v1 = acc[mi][ni][half_ * 2 + 1] + bias[col + 1];
                if (mode == 1) {
                    v0 += res[(size_t)r * N + col];
                    v1 += res[(size_t)r * N + col + 1];
                    float2 o2 = { v0, v1 };
                    *(float2*)((float*)Cv + (size_t)r * N + col) = o2;
                } else {
                    if (mode == 2) {
                        float x0 = v0, x1 = v1;
                        v0 = 0.5f * x0 * (1.f + tanhf(0.7978845608028654f *
                                                      (x0 + 0.044715f * x0 * x0 * x0)));
                        v1 = 0.5f * x1 * (1.f + tanhf(0.7978845608028654f *
                                                      (x1 + 0.044715f * x1 * x1 * x1)));
                    }
                    *(uint32_t*)((__half*)Cv + (size_t)r * N + col) = pack_h2(v0, v1);
                }
            }
        }
    }
}

// ================= Causal flash attention: cp.async K/V + ldmatrix.trans V =================
// SMEM: QP 128 rows (Q then P), K/V double-buffered 64-row tiles, all [row][APADH].
#define APADH 72
#define KVTILE_H (64*APADH)
#define ATTN_SMEM ((128 + 4*64)*APADH*2)   /* 55296 bytes */

__global__ __launch_bounds__(256)
void attn_mma(const __half* __restrict__ QKV, __half* __restrict__ O)
{
    extern __shared__ __half smA[];
    __half* QP = smA;
    uint32_t qp_b = smem_u32(QP);
    uint32_t kv_b = qp_b + 128 * APADH * 2;   // K0 | V0 | K1 | V1

    int tid = threadIdx.x, lane = tid & 31, w = tid >> 5;
    int g = lane >> 2, kq = lane & 3;
    int qb = gridDim.x - 1 - blockIdx.x;      // heavy causal tiles first
    int h = blockIdx.y, b = blockIdx.z;
    size_t base  = ((size_t)b * SEQ) * QKVN + h * HDIM;
    size_t obase = ((size_t)b * SEQ) * EMB + h * HDIM;
    int wrow = w * 16;

    int a_r  = (lane & 7) + ((lane >> 3) & 1) * 8;
    int a_k8 = (lane >> 4) * 8;
    int b_r  = (lane & 7) + (lane >> 4) * 8;
    int b_k8 = ((lane >> 3) & 1) * 8;
    // V-trans lane mapping (source rows = keys, col = d-tile)
    int vt_r  = (lane & 7) + ((lane >> 3) & 1) * 8;
    int vt_c8 = (lane >> 4) * 8;

    const __half* Kg0 = QKV + base + EMB;
    const __half* Vg0 = QKV + base + 2 * EMB;
    int ldr = tid >> 3, ldc = (tid & 7) * 8;   // 32 rows per pass, 2 passes

    // stage Q tile (128x64 halves, pre-scaled)
    #pragma unroll
    for (int u = 0; u < 4; u++) {
        int idx = tid + u * 256;
        int r = idx >> 3, c8 = (idx & 7) * 8;
        *(uint4*)(QP + r * APADH + c8) =
            *(const uint4*)(QKV + base + (size_t)(qb * 128 + r) * QKVN + c8);
    }

    int nkt = 2 * qb + 2;

    // issue K/V tile kb into buffer bi
    auto issue = [&](int kb, int bi) {
        uint32_t kaddr = kv_b + (uint32_t)bi * 2 * KVTILE_H * 2;
        uint32_t vaddr = kaddr + KVTILE_H * 2;
        const __half* Kg = Kg0 + (size_t)(kb * 64) * QKVN;
        const __half* Vg = Vg0 + (size_t)(kb * 64) * QKVN;
        #pragma unroll
        for (int u = 0; u < 2; u++) {
            int r = ldr + u * 32;
            cp_async16(kaddr + (uint32_t)(r * APADH + ldc) * 2, Kg + (size_t)r * QKVN + ldc);
            cp_async16(vaddr + (uint32_t)(r * APADH + ldc) * 2, Vg + (size_t)r * QKVN + ldc);
        }
    };

    issue(0, 0);
    cp_commit();
    __syncthreads();   // Q tile visible

    uint32_t qa[4][4];
    #pragma unroll
    for (int ks = 0; ks < 4; ks++)
        ldm_x4(qa[ks], qp_b + (uint32_t)((wrow + a_r) * APADH + ks * 16 + a_k8) * 2);

    float m0 = -1e30f, m1 = -1e30f, l0 = 0.f, l1 = 0.f;
    float o[8][4];
    #pragma unroll
    for (int ni = 0; ni < 8; ni++)
        #pragma unroll
        for (int e = 0; e < 4; e++) o[ni][e] = 0.f;

    #pragma unroll 1
    for (int kb = 0; kb < nkt; kb++) {
        int bi = kb & 1;
        if (kb + 1 < nkt) {
            issue(kb + 1, bi ^ 1);
            cp_commit();
            cp_wait<1>();
        } else {
            cp_wait<0>();
        }
        __syncthreads();

        uint32_t ks_b2 = kv_b + (uint32_t)bi * 2 * KVTILE_H * 2;
        uint32_t vs_b2 = ks_b2 + KVTILE_H * 2;

        // S = Q K^T
        float s[8][4];
        #pragma unroll
        for (int ni = 0; ni < 8; ni++)
            #pragma unroll
            for (int e = 0; e < 4; e++) s[ni][e] = 0.f;
        #pragma unroll
        for (int ks = 0; ks < 4; ks++) {
            #pragma unroll
            for (int nj = 0; nj < 4; nj++) {
                uint32_t bf[4];
                ldm_x4(bf, ks_b2 + (uint32_t)((nj * 16 + b_r) * APADH + ks * 16 + b_k8) * 2);
                mma_f16(s[2 * nj],     qa[ks][0], qa[ks][1], qa[ks][2], qa[ks][3], bf[0], bf[1]);
                mma_f16(s[2 * nj + 1], qa[ks][0], qa[ks][1], qa[ks][2], qa[ks][3], bf[2], bf[3]);
            }
        }

        if (kb >= 2 * qb) {
            int row0 = qb * 128 + wrow + g;
            int row1 = row0 + 8;
            #pragma unroll
            for (int ni = 0; ni < 8; ni++) {
                int col = kb * 64 + ni * 8 + 2 * kq;
                if (col     > row0) s[ni][0] = -1e30f;
                if (col + 1 > row0) s[ni][1] = -1e30f;
                if (col     > row1) s[ni][2] = -1e30f;
                if (col + 1 > row1) s[ni][3] = -1e30f;
            }
        }

        // online softmax (2 rows per thread)
        float rm0 = -1e30f, rm1 = -1e30f;
        #pragma unroll
        for (int ni = 0; ni < 8; ni++) {
            rm0 = fmaxf(rm0, fmaxf(s[ni][0], s[ni][1]));
            rm1 = fmaxf(rm1, fmaxf(s[ni][2], s[ni][3]));
        }
        rm0 = fmaxf(rm0, __shfl_xor_sync(0xffffffffu, rm0, 1));
        rm0 = fmaxf(rm0, __shfl_xor_sync(0xffffffffu, rm0, 2));
        rm1 = fmaxf(rm1, __shfl_xor_sync(0xffffffffu, rm1, 1));
        rm1 = fmaxf(rm1, __shfl_xor_sync(0xffffffffu, rm1, 2));
        float mn0 = fmaxf(m0, rm0), mn1 = fmaxf(m1, rm1);
        float a0 = __expf(m0 - mn0), a1 = __expf(m1 - mn1);
        float rs0 = 0.f, rs1 = 0.f;
        #pragma unroll
        for (int ni = 0; ni < 8; ni++) {
            float p0 = __expf(s[ni][0] - mn0);
            float p1 = __expf(s[ni][1] - mn0);
            float p2 = __expf(s[ni][2] - mn1);
            float p3 = __expf(s[ni][3] - mn1);
            rs0 += p0 + p1; rs1 += p2 + p3;
            int col = ni * 8 + 2 * kq;
            *(uint32_t*)(QP + (wrow + g)     * APADH + col) = pack_h2(p0, p1);
            *(uint32_t*)(QP + (wrow + g + 8) * APADH + col) = pack_h2(p2, p3);
        }
        rs0 += __shfl_xor_sync(0xffffffffu, rs0, 1);
        rs0 += __shfl_xor_sync(0xffffffffu, rs0, 2);
        rs1 += __shfl_xor_sync(0xffffffffu, rs1, 1);
        rs1 += __shfl_xor_sync(0xffffffffu, rs1, 2);
        l0 = l0 * a0 + rs0;
        l1 = l1 * a1 + rs1;
        m0 = mn0; m1 = mn1;
        #pragma unroll
        for (int ni = 0; ni < 8; ni++) {
            o[ni][0] *= a0; o[ni][1] *= a0;
            o[ni][2] *= a1; o[ni][3] *= a1;
        }
        __syncwarp();

        // ctx += P @ V  (V fragments via ldmatrix.trans on [key][d] tile)
        #pragma unroll
        for (int ks2 = 0; ks2 < 4; ks2++) {
            uint32_t pa[4];
            ldm_x4(pa, qp_b + (uint32_t)((wrow + a_r) * APADH + ks2 * 16 + a_k8) * 2);
            #pragma unroll
            for (int nj = 0; nj < 4; nj++) {
                uint32_t bf[4];
                ldm_x4_trans(bf, vs_b2 + (uint32_t)((ks2 * 16 + vt_r) * APADH + nj * 16 + vt_c8) * 2);
                mma_f16(o[2 * nj],     pa[0], pa[1], pa[2], pa[3], bf[0], bf[1]);
                mma_f16(o[2 * nj + 1], pa[0], pa[1], pa[2], pa[3], bf[2], bf[3]);
            }
        }
        __syncthreads();   // tile consumed; buffer may be overwritten next iter
    }

    float inv0 = 1.0f / l0, inv1 = 1.0f / l1;
    size_t row0 = obase + (size_t)(qb * 128 + wrow + g) * EMB;
    size_t row1 = row0 + (size_t)8 * EMB;
    #pragma unroll
    for (int ni = 0; ni < 8; ni++) {
        int col = ni * 8 + 2 * kq;
        *(uint32_t*)(O + row0 + col) = pack_h2(o[ni][0] * inv0, o[ni][1] * inv0);
        *(uint32_t*)(O + row1 + col) = pack_h2(o[ni][2] * inv1, o[ni][3] * inv1);
    }
}

// ================= launch =================
extern "C" void kernel_launch(void* const* d_in, const int* in_sizes, int n_in,
                              void* d_out, int out_size)
{
    const float* x         = (const float*)d_in[0];
    const float* Wq        = (const float*)d_in[1];
    const float* bq        = (const float*)d_in[2];
    const float* Wk        = (const float*)d_in[3];
    const float* bk        = (const float*)d_in[4];
    const float* Wv        = (const float*)d_in[5];
    const float* bv        = (const float*)d_in[6];
    const float* Wo        = (const float*)d_in[7];
    const float* bo        = (const float*)d_in[8];
    const float* W1        = (const float*)d_in[9];
    const float* b1        = (const float*)d_in[10];
    const float* W2        = (const float*)d_in[11];
    const float* b2        = (const float*)d_in[12];
    const float* ln1_scale = (const float*)d_in[13];
    const float* ln1_shift = (const float*)d_in[14];
    const float* ln2_scale = (const float*)d_in[15];
    const float* ln2_shift = (const float*)d_in[16];
    float* out = (float*)d_out;

    __half *h, *qkv, *ctx, *ff, *wtqkv, *wto, *wt1, *wt2;
    float *x2, *bqkv;
    cudaGetSymbolAddress((void**)&h,     g_h);
    cudaGetSymbolAddress((void**)&qkv,   g_qkv);
    cudaGetSymbolAddress((void**)&ctx,   g_ctx);
    cudaGetSymbolAddress((void**)&x2,    g_x2);
    cudaGetSymbolAddress((void**)&ff,    g_ff);
    cudaGetSymbolAddress((void**)&bqkv,  g_bqkv);
    cudaGetSymbolAddress((void**)&wtqkv, g_wtqkv);
    cudaGetSymbolAddress((void**)&wto,   g_wto);
    cudaGetSymbolAddress((void**)&wt1,   g_wt1);
    cudaGetSymbolAddress((void**)&wt2,   g_wt2);

    cudaFuncSetAttribute(tc_gemm,  cudaFuncAttributeMaxDynamicSharedMemorySize, GEMM_SMEM);
    cudaFuncSetAttribute(attn_mma, cudaFuncAttributeMaxDynamicSharedMemorySize, ATTN_SMEM);

    dim3 gQKV(QKVN / 128, MTOT / 128);
    dim3 gE  (EMB  / 128, MTOT / 128);
    dim3 gF  (FF   / 128, MTOT / 128);
    dim3 gA  (SEQ / 128, NHEADS, BATCH);

    prep_weights<<<12300, dim3(32, 8)>>>(Wq, Wk, Wv, Wo, W1, W2, bq, bk, bv,
                                         wtqkv, wto, wt1, wt2, bqkv);
    ln_kernel<<<MTOT, 256>>>(x, ln1_scale, ln1_shift, h);
    tc_gemm<<<gQKV, 256, GEMM_SMEM>>>(h, wtqkv, bqkv, nullptr, qkv, MTOT, QKVN, EMB, 0);
    attn_mma<<<gA, 256, ATTN_SMEM>>>(qkv, ctx);
    tc_gemm<<<gE, 256, GEMM_SMEM>>>(ctx, wto, bo, x, x2, MTOT, EMB, EMB, 1);
    ln_kernel<<<MTOT, 256>>>(x2, ln2_scale, ln2_shift, h);
    tc_gemm<<<gF, 256, GEMM_SMEM>>>(h, wt1, b1, nullptr, ff, MTOT, FF, EMB, 2);
    tc_gemm<<<gE, 256, GEMM_SMEM>>>(ff, wt2, b2, x2, out, MTOT, EMB, FF, 1);
}

// round 10
// speedup vs baseline: 2.1943x; 1.0313x over previous
#include <cuda_runtime.h>
#include <cuda_fp16.h>
#include <math.h>
#include <stdint.h>

#define BATCH 2
#define SEQ   2048
#define EMB   1024
#define NHEADS 16
#define HDIM  64
#define FF    4096
#define MTOT  (BATCH*SEQ)   /* 4096 rows */
#define QKVN  (3*EMB)       /* 3072 */

__device__ __forceinline__ uint32_t smem_u32(const void* p) {
    uint32_t a;
    asm("{ .reg .u64 t; cvta.to.shared.u64 t, %1; cvt.u32.u64 %0, t; }" : "=r"(a) : "l"(p));
    return a;
}
__device__ __forceinline__ void mma_f16(float c[4],
    uint32_t a0, uint32_t a1, uint32_t a2, uint32_t a3,
    uint32_t b0, uint32_t b1)
{
    asm volatile("mma.sync.aligned.m16n8k16.row.col.f32.f16.f16.f32 "
        "{%0,%1,%2,%3}, {%4,%5,%6,%7}, {%8,%9}, {%0,%1,%2,%3};"
        : "+f"(c[0]), "+f"(c[1]), "+f"(c[2]), "+f"(c[3])
        : "r"(a0), "r"(a1), "r"(a2), "r"(a3), "r"(b0), "r"(b1));
}
__device__ __forceinline__ void ldm_x4(uint32_t r[4], uint32_t saddr) {
    asm volatile("ldmatrix.sync.aligned.m8n8.x4.shared.b16 {%0,%1,%2,%3}, [%4];"
        : "=r"(r[0]), "=r"(r[1]), "=r"(r[2]), "=r"(r[3]) : "r"(saddr));
}
__device__ __forceinline__ void ldm_x4_trans(uint32_t r[4], uint32_t saddr) {
    asm volatile("ldmatrix.sync.aligned.m8n8.x4.trans.shared.b16 {%0,%1,%2,%3}, [%4];"
        : "=r"(r[0]), "=r"(r[1]), "=r"(r[2]), "=r"(r[3]) : "r"(saddr));
}
__device__ __forceinline__ void cp_async16(uint32_t saddr, const void* gptr) {
    asm volatile("cp.async.cg.shared.global [%0], [%1], 16;" :: "r"(saddr), "l"(gptr));
}
__device__ __forceinline__ void cp_commit() { asm volatile("cp.async.commit_group;" ::: "memory"); }
template<int N> __device__ __forceinline__ void cp_wait() {
    asm volatile("cp.async.wait_group %0;" :: "n"(N) : "memory");
}
__device__ __forceinline__ uint32_t pack_h2(float a, float b) {
    __half2 h = __floats2half2_rn(a, b);
    return *reinterpret_cast<uint32_t*>(&h);
}

#define LOG2E 1.4426950408889634f

// ================= scratch (device globals) =================
__device__ __half g_h  [MTOT*EMB];
__device__ __half g_qkv[(size_t)MTOT*QKVN];
__device__ __half g_ctx[MTOT*EMB];
__device__ float  g_x2 [MTOT*EMB];
__device__ __half g_ff [(size_t)MTOT*FF];
__device__ __half g_wtqkv[(size_t)QKVN*EMB];
__device__ __half g_wto[EMB*EMB];
__device__ __half g_wt1[(size_t)FF*EMB];
__device__ __half g_wt2[(size_t)EMB*FF];
__device__ float  g_bqkv[QKVN];

// ================= LayerNorm (ddof=1), half output =================
__global__ __launch_bounds__(256)
void ln_kernel(const float* __restrict__ x, const float* __restrict__ sc,
               const float* __restrict__ sh, __half* __restrict__ out)
{
    int row = blockIdx.x;
    const float* xr = x + (size_t)row * EMB;
    int t = threadIdx.x;
    float4 v4 = *(const float4*)(xr + t * 4);
    float v[4] = {v4.x, v4.y, v4.z, v4.w};
    __shared__ float red[8];
    float s = v[0] + v[1] + v[2] + v[3];
    #pragma unroll
    for (int o = 16; o; o >>= 1) s += __shfl_xor_sync(0xffffffffu, s, o);
    if ((t & 31) == 0) red[t >> 5] = s;
    __syncthreads();
    float tot = 0.f;
    #pragma unroll
    for (int i = 0; i < 8; i++) tot += red[i];
    float mean = tot * (1.0f / EMB);
    __syncthreads();
    float sq = 0.f;
    #pragma unroll
    for (int i = 0; i < 4; i++) { float d = v[i] - mean; sq += d * d; }
    #pragma unroll
    for (int o = 16; o; o >>= 1) sq += __shfl_xor_sync(0xffffffffu, sq, o);
    if ((t & 31) == 0) red[t >> 5] = sq;
    __syncthreads();
    float sqt = 0.f;
    #pragma unroll
    for (int i = 0; i < 8; i++) sqt += red[i];
    float rstd = rsqrtf(sqt * (1.0f / (EMB - 1)) + 1e-5f);
    float r[4];
    #pragma unroll
    for (int i = 0; i < 4; i++) {
        int c = t * 4 + i;
        r[i] = sc[c] * (v[i] - mean) * rstd + sh[c];
    }
    uint2 st = { pack_h2(r[0], r[1]), pack_h2(r[2], r[3]) };
    *(uint2*)(out + (size_t)row * EMB + t * 4) = st;
}

// ================= fused weight prep =================
// Wq/bq carry 0.125 * log2(e): attention softmax runs in exp2 domain.
__global__ __launch_bounds__(256)
void prep_weights(const float* __restrict__ Wq, const float* __restrict__ Wk,
                  const float* __restrict__ Wv, const float* __restrict__ Wo,
                  const float* __restrict__ W1, const float* __restrict__ W2,
                  const float* __restrict__ bq, const float* __restrict__ bk,
                  const float* __restrict__ bv,
                  __half* __restrict__ wtqkv, __half* __restrict__ wto,
                  __half* __restrict__ wt1, __half* __restrict__ wt2,
                  float* __restrict__ bqkv)
{
    int bid = blockIdx.x;
    int tx = threadIdx.x, ty = threadIdx.y;
    if (bid >= 12288) {
        int i = (bid - 12288) * 256 + ty * 32 + tx;
        if (i < EMB)            bqkv[i] = bq[i] * (0.125f * LOG2E);
        else if (i < 2 * EMB)   bqkv[i] = bk[i - EMB];
        else if (i < 3 * EMB)   bqkv[i] = bv[i - 2 * EMB];
        return;
    }
    const float* W; __half* Wt; int K, N, tiles_x, t; float scale = 1.f;
    if (bid < 3072) {
        int w = bid >> 10; t = bid & 1023;
        W = (w == 0) ? Wq : (w == 1) ? Wk : Wv;
        Wt = wtqkv + (size_t)w * EMB * EMB;
        K = EMB; N = EMB; tiles_x = 32;
        if (w == 0) scale = 0.125f * LOG2E;
    } else if (bid < 4096) {
        t = bid - 3072; W = Wo; Wt = wto; K = EMB; N = EMB; tiles_x = 32;
    } else if (bid < 8192) {
        t = bid - 4096; W = W1; Wt = wt1; K = EMB; N = FF; tiles_x = 128;
    } else {
        t = bid - 8192; W = W2; Wt = wt2; K = FF; N = EMB; tiles_x = 32;
    }
    int x0 = (t % tiles_x) * 32, y0 = (t / tiles_x) * 32;
    __shared__ float tile[32][33];
    #pragma unroll
    for (int j = 0; j < 32; j += 8)
        tile[ty + j][tx] = W[(size_t)(y0 + ty + j) * N + x0 + tx];
    __syncthreads();
    #pragma unroll
    for (int j = 0; j < 32; j += 8)
        Wt[(size_t)(x0 + ty + j) * K + y0 + tx] = __float2half(tile[tx][ty + j] * scale);
}

// ================= fp16 mma.sync GEMM (unchanged) =================
#define PADH 40
#define TILE_H (128*PADH)
#define STAGE_B (2*TILE_H*2)
#define GEMM_SMEM (4*STAGE_B)

__global__ __launch_bounds__(256, 2)
void tc_gemm(const __half* __restrict__ A, const __half* __restrict__ Bt,
             const float* __restrict__ bias, const float* __restrict__ res,
             void* __restrict__ Cv, int M, int N, int K, int mode)
{
    extern __shared__ __half smh[];
    uint32_t sb = smem_u32(smh);

    int tid  = threadIdx.x;
    int lane = tid & 31, wid = tid >> 5;
    int g    = lane >> 2;
    int kq   = lane & 3;
    int wm   = wid & 1;
    int wn   = wid >> 1;
    int bcol = blockIdx.x * 128, brow = blockIdx.y * 128;

    int a_r  = (lane & 7) + ((lane >> 3) & 1) * 8;
    int a_k8 = (lane >> 4) * 8;
    int b_r  = (lane & 7) + (lane >> 4) * 8;
    int b_k8 = ((lane >> 3) & 1) * 8;

    const __half* Ap = A  + (size_t)brow * K;
    const __half* Bp = Bt + (size_t)bcol * K;

    int lr[2], lc[2];
    #pragma unroll
    for (int u = 0; u < 2; u++) {
        int idx = tid + u * 256;
        lr[u] = idx >> 2;
        lc[u] = idx & 3;
    }

    float acc[4][4][4];
    #pragma unroll
    for (int mi = 0; mi < 4; mi++)
        #pragma unroll
        for (int ni = 0; ni < 4; ni++)
            #pragma unroll
            for (int e = 0; e < 4; e++) acc[mi][ni][e] = 0.f;

    int nk = K >> 5;

    #pragma unroll
    for (int s = 0; s < 3; s++) {
        uint32_t abase = sb + (uint32_t)s * STAGE_B;
        uint32_t bbase = abase + TILE_H * 2;
        const __half* Ag = Ap + s * 32;
        const __half* Bg = Bp + s * 32;
        #pragma unroll
        for (int u = 0; u < 2; u++) {
            cp_async16(abase + (uint32_t)(lr[u] * 80 + lc[u] * 16), Ag + (size_t)lr[u] * K + lc[u] * 8);
            cp_async16(bbase + (uint32_t)(lr[u] * 80 + lc[u] * 16), Bg + (size_t)lr[u] * K + lc[u] * 8);
        }
        cp_commit();
    }

    #pragma unroll 1
    for (int kt = 0; kt < nk; kt++) {
        cp_wait<2>();
        __syncthreads();

        if (kt + 3 < nk) {
            int s = (kt + 3) & 3;
            uint32_t abase = sb + (uint32_t)s * STAGE_B;
            uint32_t bbase = abase + TILE_H * 2;
            const __half* Ag = Ap + (kt + 3) * 32;
            const __half* Bg = Bp + (kt + 3) * 32;
            #pragma unroll
            for (int u = 0; u < 2; u++) {
                cp_async16(abase + (uint32_t)(lr[u] * 80 + lc[u] * 16), Ag + (size_t)lr[u] * K + lc[u] * 8);
                cp_async16(bbase + (uint32_t)(lr[u] * 80 + lc[u] * 16), Bg + (size_t)lr[u] * K + lc[u] * 8);
            }
        }
        cp_commit();

        uint32_t As_b = sb + (uint32_t)(kt & 3) * STAGE_B;
        uint32_t Bs_b = As_b + TILE_H * 2;
        #pragma unroll
        for (int ks = 0; ks < 2; ks++) {
            int k0 = ks * 16;
            uint32_t af[4][4], bf[4][2];
            #pragma unroll
            for (int mi = 0; mi < 4; mi++)
                ldm_x4(af[mi], As_b + (uint32_t)((wm * 64 + mi * 16 + a_r) * PADH + k0 + a_k8) * 2);
            #pragma unroll
            for (int nj = 0; nj < 2; nj++)
                ldm_x4(&bf[2 * nj][0], Bs_b + (uint32_t)((wn * 32 + nj * 16 + b_r) * PADH + k0 + b_k8) * 2);
            #pragma unroll
            for (int mi = 0; mi < 4; mi++)
                #pragma unroll
                for (int ni = 0; ni < 4; ni++)
                    mma_f16(acc[mi][ni], af[mi][0], af[mi][1], af[mi][2], af[mi][3],
                            bf[ni][0], bf[ni][1]);
        }
    }

    #pragma unroll
    for (int mi = 0; mi < 4; mi++) {
        #pragma unroll
        for (int ni = 0; ni < 4; ni++) {
            int row = brow + wm * 64 + mi * 16 + g;
            int col = bcol + wn * 32 + ni * 8 + 2 * kq;
            #pragma unroll
            for (int half_ = 0; half_ < 2; half_++) {
                int r = row + half_ * 8;
                float v0 = acc[mi][ni][half_ * 2 + 0] + bias[col];
                float v1 = acc[mi][ni][half_ * 2 + 1] + bias[col + 1];
                if (mode == 1) {
                    v0 += res[(size_t)r * N + col];
                    v1 += res[(size_t)r * N + col + 1];
                    float2 o2 = { v0, v1 };
                    *(float2*)((float*)Cv + (size_t)r * N + col) = o2;
                } else {
                    if (mode == 2) {
                        float x0 = v0, x1 = v1;
                        v0 = 0.5f * x0 * (1.f + tanhf(0.7978845608028654f *
                                                      (x0 + 0.044715f * x0 * x0 * x0)));
                        v1 = 0.5f * x1 * (1.f + tanhf(0.7978845608028654f *
                                                      (x1 + 0.044715f * x1 * x1 * x1)));
                    }
                    *(uint32_t*)((__half*)Cv + (size_t)r * N + col) = pack_h2(v0, v1);
                }
            }
        }
    }
}

// ================= Causal flash attention: reg-resident P, exp2, 1 sync/tile =================
// SMEM: Q 128 rows, K/V 3-buffer ring of 64-row tiles, all [row][APADH].
#define APADH 72
#define KVTILE_H (64*APADH)
#define ATTN_SMEM ((128 + 6*64)*APADH*2)   /* 73728 bytes */

__global__ __launch_bounds__(256)
void attn_mma(const __half* __restrict__ QKV, __half* __restrict__ O)
{
    extern __shared__ __half smA[];
    __half* QP = smA;
    uint32_t qp_b = smem_u32(QP);
    uint32_t kv_b = qp_b + 128 * APADH * 2;   // 3 x (K|V) buffers

    int tid = threadIdx.x, lane = tid & 31, w = tid >> 5;
    int g = lane >> 2, kq = lane & 3;
    int qb = gridDim.x - 1 - blockIdx.x;      // heavy causal tiles first
    int h = blockIdx.y, b = blockIdx.z;
    size_t base  = ((size_t)b * SEQ) * QKVN + h * HDIM;
    size_t obase = ((size_t)b * SEQ) * EMB + h * HDIM;
    int wrow = w * 16;

    int a_r  = (lane & 7) + ((lane >> 3) & 1) * 8;
    int a_k8 = (lane >> 4) * 8;
    int b_r  = (lane & 7) + (lane >> 4) * 8;
    int b_k8 = ((lane >> 3) & 1) * 8;
    int vt_r  = (lane & 7) + ((lane >> 3) & 1) * 8;
    int vt_c8 = (lane >> 4) * 8;

    const __half* Kg0 = QKV + base + EMB;
    const __half* Vg0 = QKV + base + 2 * EMB;
    int ldr = tid >> 3, ldc = (tid & 7) * 8;

    // stage Q tile (128x64 halves, pre-scaled into exp2 domain)
    #pragma unroll
    for (int u = 0; u < 4; u++) {
        int idx = tid + u * 256;
        int r = idx >> 3, c8 = (idx & 7) * 8;
        *(uint4*)(QP + r * APADH + c8) =
            *(const uint4*)(QKV + base + (size_t)(qb * 128 + r) * QKVN + c8);
    }

    int nkt = 2 * qb + 2;

    auto issue = [&](int kb, int bi) {
        uint32_t kaddr = kv_b + (uint32_t)bi * 2 * KVTILE_H * 2;
        uint32_t vaddr = kaddr + KVTILE_H * 2;
        const __half* Kg = Kg0 + (size_t)(kb * 64) * QKVN;
        const __half* Vg = Vg0 + (size_t)(kb * 64) * QKVN;
        #pragma unroll
        for (int u = 0; u < 2; u++) {
            int r = ldr + u * 32;
            cp_async16(kaddr + (uint32_t)(r * APADH + ldc) * 2, Kg + (size_t)r * QKVN + ldc);
            cp_async16(vaddr + (uint32_t)(r * APADH + ldc) * 2, Vg + (size_t)r * QKVN + ldc);
        }
    };

    issue(0, 0); cp_commit();
    issue(1, 1); cp_commit();
    __syncthreads();   // Q visible

    uint32_t qa[4][4];
    #pragma unroll
    for (int ks = 0; ks < 4; ks++)
        ldm_x4(qa[ks], qp_b + (uint32_t)((wrow + a_r) * APADH + ks * 16 + a_k8) * 2);

    float m0 = -1e30f, m1 = -1e30f, l0 = 0.f, l1 = 0.f;
    float o[8][4];
    #pragma unroll
    for (int ni = 0; ni < 8; ni++)
        #pragma unroll
        for (int e = 0; e < 4; e++) o[ni][e] = 0.f;

    #pragma unroll 1
    for (int kb = 0; kb < nkt; kb++) {
        int bi = kb % 3;
        cp_wait<1>();        // tile kb landed (this thread)
        __syncthreads();     // all threads' copies visible; prev reads of reused buf done
        if (kb + 2 < nkt) issue(kb + 2, (kb + 2) % 3);
        cp_commit();         // always commit: uniform group accounting

        // fully-masked warp on the diagonal's upper tile: skip all math
        bool active = (kb * 64) <= (qb * 128 + wrow + 15);
        if (active) {
            uint32_t ks_b2 = kv_b + (uint32_t)bi * 2 * KVTILE_H * 2;
            uint32_t vs_b2 = ks_b2 + KVTILE_H * 2;

            // S = Q K^T (exp2 domain)
            float s[8][4];
            #pragma unroll
            for (int ni = 0; ni < 8; ni++)
                #pragma unroll
                for (int e = 0; e < 4; e++) s[ni][e] = 0.f;
            #pragma unroll
            for (int ks = 0; ks < 4; ks++) {
                #pragma unroll
                for (int nj = 0; nj < 4; nj++) {
                    uint32_t bf[4];
                    ldm_x4(bf, ks_b2 + (uint32_t)((nj * 16 + b_r) * APADH + ks * 16 + b_k8) * 2);
                    mma_f16(s[2 * nj],     qa[ks][0], qa[ks][1], qa[ks][2], qa[ks][3], bf[0], bf[1]);
                    mma_f16(s[2 * nj + 1], qa[ks][0], qa[ks][1], qa[ks][2], qa[ks][3], bf[2], bf[3]);
                }
            }

            if (kb >= 2 * qb) {
                int row0 = qb * 128 + wrow + g;
                int row1 = row0 + 8;
                #pragma unroll
                for (int ni = 0; ni < 8; ni++) {
                    int col = kb * 64 + ni * 8 + 2 * kq;
                    if (col     > row0) s[ni][0] = -1e30f;
                    if (col + 1 > row0) s[ni][1] = -1e30f;
                    if (col     > row1) s[ni][2] = -1e30f;
                    if (col + 1 > row1) s[ni][3] = -1e30f;
                }
            }

            // online softmax (exp2 domain), P kept as fp16 fragments in registers
            float rm0 = -1e30f, rm1 = -1e30f;
            #pragma unroll
            for (int ni = 0; ni < 8; ni++) {
                rm0 = fmaxf(rm0, fmaxf(s[ni][0], s[ni][1]));
                rm1 = fmaxf(rm1, fmaxf(s[ni][2], s[ni][3]));
            }
            rm0 = fmaxf(rm0, __shfl_xor_sync(0xffffffffu, rm0, 1));
            rm0 = fmaxf(rm0, __shfl_xor_sync(0xffffffffu, rm0, 2));
            rm1 = fmaxf(rm1, __shfl_xor_sync(0xffffffffu, rm1, 1));
            rm1 = fmaxf(rm1, __shfl_xor_sync(0xffffffffu, rm1, 2));
            float mn0 = fmaxf(m0, rm0), mn1 = fmaxf(m1, rm1);
            float a0 = exp2f(m0 - mn0), a1 = exp2f(m1 - mn1);
            float rs0 = 0.f, rs1 = 0.f;
            uint32_t pp[8][2];
            #pragma unroll
            for (int ni = 0; ni < 8; ni++) {
                float p0 = exp2f(s[ni][0] - mn0);
                float p1 = exp2f(s[ni][1] - mn0);
                float p2 = exp2f(s[ni][2] - mn1);
                float p3 = exp2f(s[ni][3] - mn1);
                rs0 += p0 + p1; rs1 += p2 + p3;
                pp[ni][0] = pack_h2(p0, p1);
                pp[ni][1] = pack_h2(p2, p3);
            }
            rs0 += __shfl_xor_sync(0xffffffffu, rs0, 1);
            rs0 += __shfl_xor_sync(0xffffffffu, rs0, 2);
            rs1 += __shfl_xor_sync(0xffffffffu, rs1, 1);
            rs1 += __shfl_xor_sync(0xffffffffu, rs1, 2);
            l0 = l0 * a0 + rs0;
            l1 = l1 * a1 + rs1;
            m0 = mn0; m1 = mn1;
            #pragma unroll
            for (int ni = 0; ni < 8; ni++) {
                o[ni][0] *= a0; o[ni][1] *= a0;
                o[ni][2] *= a1; o[ni][3] *= a1;
            }

            // ctx += P @ V : P fragments direct from registers, V via ldmatrix.trans
            #pragma unroll
            for (int ks2 = 0; ks2 < 4; ks2++) {
                uint32_t pa0 = pp[2 * ks2][0],     pa1 = pp[2 * ks2][1];
                uint32_t pa2 = pp[2 * ks2 + 1][0], pa3 = pp[2 * ks2 + 1][1];
                #pragma unroll
                for (int nj = 0; nj < 4; nj++) {
                    uint32_t bf[4];
                    ldm_x4_trans(bf, vs_b2 + (uint32_t)((ks2 * 16 + vt_r) * APADH + nj * 16 + vt_c8) * 2);
                    mma_f16(o[2 * nj],     pa0, pa1, pa2, pa3, bf[0], bf[1]);
                    mma_f16(o[2 * nj + 1], pa0, pa1, pa2, pa3, bf[2], bf[3]);
                }
            }
        }
    }

    float inv0 = 1.0f / l0, inv1 = 1.0f / l1;
    size_t row0 = obase + (size_t)(qb * 128 + wrow + g) * EMB;
    size_t row1 = row0 + (size_t)8 * EMB;
    #pragma unroll
    for (int ni = 0; ni < 8; ni++) {
        int col = ni * 8 + 2 * kq;
        *(uint32_t*)(O + row0 + col) = pack_h2(o[ni][0] * inv0, o[ni][1] * inv0);
        *(uint32_t*)(O + row1 + col) = pack_h2(o[ni][2] * inv1, o[ni][3] * inv1);
    }
}

// ================= launch =================
extern "C" void kernel_launch(void* const* d_in, const int* in_sizes, int n_in,
                              void* d_out, int out_size)
{
    const float* x         = (const float*)d_in[0];
    const float* Wq        = (const float*)d_in[1];
    const float* bq        = (const float*)d_in[2];
    const float* Wk        = (const float*)d_in[3];
    const float* bk        = (const float*)d_in[4];
    const float* Wv        = (const float*)d_in[5];
    const float* bv        = (const float*)d_in[6];
    const float* Wo        = (const float*)d_in[7];
    const float* bo        = (const float*)d_in[8];
    const float* W1        = (const float*)d_in[9];
    const float* b1        = (const float*)d_in[10];
    const float* W2        = (const float*)d_in[11];
    const float* b2        = (const float*)d_in[12];
    const float* ln1_scale = (const float*)d_in[13];
    const float* ln1_shift = (const float*)d_in[14];
    const float* ln2_scale = (const float*)d_in[15];
    const float* ln2_shift = (const float*)d_in[16];
    float* out = (float*)d_out;

    __half *h, *qkv, *ctx, *ff, *wtqkv, *wto, *wt1, *wt2;
    float *x2, *bqkv;
    cudaGetSymbolAddress((void**)&h,     g_h);
    cudaGetSymbolAddress((void**)&qkv,   g_qkv);
    cudaGetSymbolAddress((void**)&ctx,   g_ctx);
    cudaGetSymbolAddress((void**)&x2,    g_x2);
    cudaGetSymbolAddress((void**)&ff,    g_ff);
    cudaGetSymbolAddress((void**)&bqkv,  g_bqkv);
    cudaGetSymbolAddress((void**)&wtqkv, g_wtqkv);
    cudaGetSymbolAddress((void**)&wto,   g_wto);
    cudaGetSymbolAddress((void**)&wt1,   g_wt1);
    cudaGetSymbolAddress((void**)&wt2,   g_wt2);

    cudaFuncSetAttribute(tc_gemm,  cudaFuncAttributeMaxDynamicSharedMemorySize, GEMM_SMEM);
    cudaFuncSetAttribute(attn_mma, cudaFuncAttributeMaxDynamicSharedMemorySize, ATTN_SMEM);

    dim3 gQKV(QKVN / 128, MTOT / 128);
    dim3 gE  (EMB  / 128, MTOT / 128);
    dim3 gF  (FF   / 128, MTOT / 128);
    dim3 gA  (SEQ / 128, NHEADS, BATCH);

    prep_weights<<<12300, dim3(32, 8)>>>(Wq, Wk, Wv, Wo, W1, W2, bq, bk, bv,
                                         wtqkv, wto, wt1, wt2, bqkv);
    ln_kernel<<<MTOT, 256>>>(x, ln1_scale, ln1_shift, h);
    tc_gemm<<<gQKV, 256, GEMM_SMEM>>>(h, wtqkv, bqkv, nullptr, qkv, MTOT, QKVN, EMB, 0);
    attn_mma<<<gA, 256, ATTN_SMEM>>>(qkv, ctx);
    tc_gemm<<<gE, 256, GEMM_SMEM>>>(ctx, wto, bo, x, x2, MTOT, EMB, EMB, 1);
    ln_kernel<<<MTOT, 256>>>(x2, ln2_scale, ln2_shift, h);
    tc_gemm<<<gF, 256, GEMM_SMEM>>>(h, wt1, b1, nullptr, ff, MTOT, FF, EMB, 2);
    tc_gemm<<<gE, 256, GEMM_SMEM>>>(ff, wt2, b2, x2, out, MTOT, EMB, FF, 1);
}

// round 11
// speedup vs baseline: 2.2058x; 1.0053x over previous
#include <cuda_runtime.h>
#include <cuda_fp16.h>
#include <math.h>
#include <stdint.h>

#define BATCH 2
#define SEQ   2048
#define EMB   1024
#define NHEADS 16
#define HDIM  64
#define FF    4096
#define MTOT  (BATCH*SEQ)   /* 4096 rows */
#define QKVN  (3*EMB)       /* 3072 */

__device__ __forceinline__ uint32_t smem_u32(const void* p) {
    uint32_t a;
    asm("{ .reg .u64 t; cvta.to.shared.u64 t, %1; cvt.u32.u64 %0, t; }" : "=r"(a) : "l"(p));
    return a;
}
__device__ __forceinline__ void mma_f16(float c[4],
    uint32_t a0, uint32_t a1, uint32_t a2, uint32_t a3,
    uint32_t b0, uint32_t b1)
{
    asm volatile("mma.sync.aligned.m16n8k16.row.col.f32.f16.f16.f32 "
        "{%0,%1,%2,%3}, {%4,%5,%6,%7}, {%8,%9}, {%0,%1,%2,%3};"
        : "+f"(c[0]), "+f"(c[1]), "+f"(c[2]), "+f"(c[3])
        : "r"(a0), "r"(a1), "r"(a2), "r"(a3), "r"(b0), "r"(b1));
}
__device__ __forceinline__ void ldm_x4(uint32_t r[4], uint32_t saddr) {
    asm volatile("ldmatrix.sync.aligned.m8n8.x4.shared.b16 {%0,%1,%2,%3}, [%4];"
        : "=r"(r[0]), "=r"(r[1]), "=r"(r[2]), "=r"(r[3]) : "r"(saddr));
}
__device__ __forceinline__ void ldm_x4_trans(uint32_t r[4], uint32_t saddr) {
    asm volatile("ldmatrix.sync.aligned.m8n8.x4.trans.shared.b16 {%0,%1,%2,%3}, [%4];"
        : "=r"(r[0]), "=r"(r[1]), "=r"(r[2]), "=r"(r[3]) : "r"(saddr));
}
__device__ __forceinline__ void cp_async16(uint32_t saddr, const void* gptr) {
    asm volatile("cp.async.cg.shared.global [%0], [%1], 16;" :: "r"(saddr), "l"(gptr));
}
__device__ __forceinline__ void cp_commit() { asm volatile("cp.async.commit_group;" ::: "memory"); }
template<int N> __device__ __forceinline__ void cp_wait() {
    asm volatile("cp.async.wait_group %0;" :: "n"(N) : "memory");
}
__device__ __forceinline__ uint32_t pack_h2(float a, float b) {
    __half2 h = __floats2half2_rn(a, b);
    return *reinterpret_cast<uint32_t*>(&h);
}
__device__ __forceinline__ uint32_t h2exp2(uint32_t x) {
    uint32_t y;
    asm("ex2.approx.f16x2 %0, %1;" : "=r"(y) : "r"(x));
    return y;
}

#define LOG2E 1.4426950408889634f

// ================= scratch (device globals) =================
__device__ __half g_h  [MTOT*EMB];
__device__ __half g_qkv[(size_t)MTOT*QKVN];
__device__ __half g_ctx[MTOT*EMB];
__device__ float  g_x2 [MTOT*EMB];
__device__ __half g_ff [(size_t)MTOT*FF];
__device__ __half g_wtqkv[(size_t)QKVN*EMB];
__device__ __half g_wto[EMB*EMB];
__device__ __half g_wt1[(size_t)FF*EMB];
__device__ __half g_wt2[(size_t)EMB*FF];
__device__ float  g_bqkv[QKVN];

// ================= LayerNorm (ddof=1), warp-per-row, half output =================
__global__ __launch_bounds__(256)
void ln_kernel(const float* __restrict__ x, const float* __restrict__ sc,
               const float* __restrict__ sh, __half* __restrict__ out)
{
    int row  = blockIdx.x * 8 + (threadIdx.x >> 5);
    int lane = threadIdx.x & 31;
    const float* xr = x + (size_t)row * EMB;

    float4 v[8];
    #pragma unroll
    for (int i = 0; i < 8; i++)
        v[i] = *(const float4*)(xr + lane * 4 + i * 128);

    float s = 0.f;
    #pragma unroll
    for (int i = 0; i < 8; i++) s += v[i].x + v[i].y + v[i].z + v[i].w;
    #pragma unroll
    for (int o = 16; o; o >>= 1) s += __shfl_xor_sync(0xffffffffu, s, o);
    float mean = s * (1.0f / EMB);

    float sq = 0.f;
    #pragma unroll
    for (int i = 0; i < 8; i++) {
        float d0 = v[i].x - mean, d1 = v[i].y - mean;
        float d2 = v[i].z - mean, d3 = v[i].w - mean;
        sq += d0 * d0 + d1 * d1 + d2 * d2 + d3 * d3;
    }
    #pragma unroll
    for (int o = 16; o; o >>= 1) sq += __shfl_xor_sync(0xffffffffu, sq, o);
    float rstd = rsqrtf(sq * (1.0f / (EMB - 1)) + 1e-5f);

    #pragma unroll
    for (int i = 0; i < 8; i++) {
        int c = lane * 4 + i * 128;
        float4 scv = *(const float4*)(sc + c);
        float4 shv = *(const float4*)(sh + c);
        float r0 = scv.x * (v[i].x - mean) * rstd + shv.x;
        float r1 = scv.y * (v[i].y - mean) * rstd + shv.y;
        float r2 = scv.z * (v[i].z - mean) * rstd + shv.z;
        float r3 = scv.w * (v[i].w - mean) * rstd + shv.w;
        uint2 st = { pack_h2(r0, r1), pack_h2(r2, r3) };
        *(uint2*)(out + (size_t)row * EMB + c) = st;
    }
}

// ================= fused weight prep =================
// Wq/bq carry 0.125 * log2(e): attention softmax runs in exp2 domain.
__global__ __launch_bounds__(256)
void prep_weights(const float* __restrict__ Wq, const float* __restrict__ Wk,
                  const float* __restrict__ Wv, const float* __restrict__ Wo,
                  const float* __restrict__ W1, const float* __restrict__ W2,
                  const float* __restrict__ bq, const float* __restrict__ bk,
                  const float* __restrict__ bv,
                  __half* __restrict__ wtqkv, __half* __restrict__ wto,
                  __half* __restrict__ wt1, __half* __restrict__ wt2,
                  float* __restrict__ bqkv)
{
    int bid = blockIdx.x;
    int tx = threadIdx.x, ty = threadIdx.y;
    if (bid >= 12288) {
        int i = (bid - 12288) * 256 + ty * 32 + tx;
        if (i < EMB)            bqkv[i] = bq[i] * (0.125f * LOG2E);
        else if (i < 2 * EMB)   bqkv[i] = bk[i - EMB];
        else if (i < 3 * EMB)   bqkv[i] = bv[i - 2 * EMB];
        return;
    }
    const float* W; __half* Wt; int K, N, tiles_x, t; float scale = 1.f;
    if (bid < 3072) {
        int w = bid >> 10; t = bid & 1023;
        W = (w == 0) ? Wq : (w == 1) ? Wk : Wv;
        Wt = wtqkv + (size_t)w * EMB * EMB;
        K = EMB; N = EMB; tiles_x = 32;
        if (w == 0) scale = 0.125f * LOG2E;
    } else if (bid < 4096) {
        t = bid - 3072; W = Wo; Wt = wto; K = EMB; N = EMB; tiles_x = 32;
    } else if (bid < 8192) {
        t = bid - 4096; W = W1; Wt = wt1; K = EMB; N = FF; tiles_x = 128;
    } else {
        t = bid - 8192; W = W2; Wt = wt2; K = FF; N = EMB; tiles_x = 32;
    }
    int x0 = (t % tiles_x) * 32, y0 = (t / tiles_x) * 32;
    __shared__ float tile[32][33];
    #pragma unroll
    for (int j = 0; j < 32; j += 8)
        tile[ty + j][tx] = W[(size_t)(y0 + ty + j) * N + x0 + tx];
    __syncthreads();
    #pragma unroll
    for (int j = 0; j < 32; j += 8)
        Wt[(size_t)(x0 + ty + j) * K + y0 + tx] = __float2half(tile[tx][ty + j] * scale);
}

// ================= fp16 mma.sync GEMM (unchanged) =================
#define PADH 40
#define TILE_H (128*PADH)
#define STAGE_B (2*TILE_H*2)
#define GEMM_SMEM (4*STAGE_B)

__global__ __launch_bounds__(256, 2)
void tc_gemm(const __half* __restrict__ A, const __half* __restrict__ Bt,
             const float* __restrict__ bias, const float* __restrict__ res,
             void* __restrict__ Cv, int M, int N, int K, int mode)
{
    extern __shared__ __half smh[];
    uint32_t sb = smem_u32(smh);

    int tid  = threadIdx.x;
    int lane = tid & 31, wid = tid >> 5;
    int g    = lane >> 2;
    int kq   = lane & 3;
    int wm   = wid & 1;
    int wn   = wid >> 1;
    int bcol = blockIdx.x * 128, brow = blockIdx.y * 128;

    int a_r  = (lane & 7) + ((lane >> 3) & 1) * 8;
    int a_k8 = (lane >> 4) * 8;
    int b_r  = (lane & 7) + (lane >> 4) * 8;
    int b_k8 = ((lane >> 3) & 1) * 8;

    const __half* Ap = A  + (size_t)brow * K;
    const __half* Bp = Bt + (size_t)bcol * K;

    int lr[2], lc[2];
    #pragma unroll
    for (int u = 0; u < 2; u++) {
        int idx = tid + u * 256;
        lr[u] = idx >> 2;
        lc[u] = idx & 3;
    }

    float acc[4][4][4];
    #pragma unroll
    for (int mi = 0; mi < 4; mi++)
        #pragma unroll
        for (int ni = 0; ni < 4; ni++)
            #pragma unroll
            for (int e = 0; e < 4; e++) acc[mi][ni][e] = 0.f;

    int nk = K >> 5;

    #pragma unroll
    for (int s = 0; s < 3; s++) {
        uint32_t abase = sb + (uint32_t)s * STAGE_B;
        uint32_t bbase = abase + TILE_H * 2;
        const __half* Ag = Ap + s * 32;
        const __half* Bg = Bp + s * 32;
        #pragma unroll
        for (int u = 0; u < 2; u++) {
            cp_async16(abase + (uint32_t)(lr[u] * 80 + lc[u] * 16), Ag + (size_t)lr[u] * K + lc[u] * 8);
            cp_async16(bbase + (uint32_t)(lr[u] * 80 + lc[u] * 16), Bg + (size_t)lr[u] * K + lc[u] * 8);
        }
        cp_commit();
    }

    #pragma unroll 1
    for (int kt = 0; kt < nk; kt++) {
        cp_wait<2>();
        __syncthreads();

        if (kt + 3 < nk) {
            int s = (kt + 3) & 3;
            uint32_t abase = sb + (uint32_t)s * STAGE_B;
            uint32_t bbase = abase + TILE_H * 2;
            const __half* Ag = Ap + (kt + 3) * 32;
            const __half* Bg = Bp + (kt + 3) * 32;
            #pragma unroll
            for (int u = 0; u < 2; u++) {
                cp_async16(abase + (uint32_t)(lr[u] * 80 + lc[u] * 16), Ag + (size_t)lr[u] * K + lc[u] * 8);
                cp_async16(bbase + (uint32_t)(lr[u] * 80 + lc[u] * 16), Bg + (size_t)lr[u] * K + lc[u] * 8);
            }
        }
        cp_commit();

        uint32_t As_b = sb + (uint32_t)(kt & 3) * STAGE_B;
        uint32_t Bs_b = As_b + TILE_H * 2;
        #pragma unroll
        for (int ks = 0; ks < 2; ks++) {
            int k0 = ks * 16;
            uint32_t af[4][4], bf[4][2];
            #pragma unroll
            for (int mi = 0; mi < 4; mi++)
                ldm_x4(af[mi], As_b + (uint32_t)((wm * 64 + mi * 16 + a_r) * PADH + k0 + a_k8) * 2);
            #pragma unroll
            for (int nj = 0; nj < 2; nj++)
                ldm_x4(&bf[2 * nj][0], Bs_b + (uint32_t)((wn * 32 + nj * 16 + b_r) * PADH + k0 + b_k8) * 2);
            #pragma unroll
            for (int mi = 0; mi < 4; mi++)
                #pragma unroll
                for (int ni = 0; ni < 4; ni++)
                    mma_f16(acc[mi][ni], af[mi][0], af[mi][1], af[mi][2], af[mi][3],
                            bf[ni][0], bf[ni][1]);
        }
    }

    #pragma unroll
    for (int mi = 0; mi < 4; mi++) {
        #pragma unroll
        for (int ni = 0; ni < 4; ni++) {
            int row = brow + wm * 64 + mi * 16 + g;
            int col = bcol + wn * 32 + ni * 8 + 2 * kq;
            #pragma unroll
            for (int half_ = 0; half_ < 2; half_++) {
                int r = row + half_ * 8;
                float v0 = acc[mi][ni][half_ * 2 + 0] + bias[col];
                float v1 = acc[mi][ni][half_ * 2 + 1] + bias[col + 1];
                if (mode == 1) {
                    v0 += res[(size_t)r * N + col];
                    v1 += res[(size_t)r * N + col + 1];
                    float2 o2 = { v0, v1 };
                    *(float2*)((float*)Cv + (size_t)r * N + col) = o2;
                } else {
                    if (mode == 2) {
                        float x0 = v0, x1 = v1;
                        v0 = 0.5f * x0 * (1.f + tanhf(0.7978845608028654f *
                                                      (x0 + 0.044715f * x0 * x0 * x0)));
                        v1 = 0.5f * x1 * (1.f + tanhf(0.7978845608028654f *
                                                      (x1 + 0.044715f * x1 * x1 * x1)));
                    }
                    *(uint32_t*)((__half*)Cv + (size_t)r * N + col) = pack_h2(v0, v1);
                }
            }
        }
    }
}

// ================= Causal flash attention: reg P, f16x2 exp2, 1 sync/tile =================
#define APADH 72
#define KVTILE_H (64*APADH)
#define ATTN_SMEM ((128 + 6*64)*APADH*2)   /* 73728 bytes */

__global__ __launch_bounds__(256, 2)
void attn_mma(const __half* __restrict__ QKV, __half* __restrict__ O)
{
    extern __shared__ __half smA[];
    __half* QP = smA;
    uint32_t qp_b = smem_u32(QP);
    uint32_t kv_b = qp_b + 128 * APADH * 2;   // 3 x (K|V) buffers

    int tid = threadIdx.x, lane = tid & 31, w = tid >> 5;
    int g = lane >> 2, kq = lane & 3;
    int qb = gridDim.x - 1 - blockIdx.x;      // heavy causal tiles first
    int h = blockIdx.y, b = blockIdx.z;
    size_t base  = ((size_t)b * SEQ) * QKVN + h * HDIM;
    size_t obase = ((size_t)b * SEQ) * EMB + h * HDIM;
    int wrow = w * 16;

    int a_r  = (lane & 7) + ((lane >> 3) & 1) * 8;
    int a_k8 = (lane >> 4) * 8;
    int b_r  = (lane & 7) + (lane >> 4) * 8;
    int b_k8 = ((lane >> 3) & 1) * 8;
    int vt_r  = (lane & 7) + ((lane >> 3) & 1) * 8;
    int vt_c8 = (lane >> 4) * 8;

    const __half* Kg0 = QKV + base + EMB;
    const __half* Vg0 = QKV + base + 2 * EMB;
    int ldr = tid >> 3, ldc = (tid & 7) * 8;

    #pragma unroll
    for (int u = 0; u < 4; u++) {
        int idx = tid + u * 256;
        int r = idx >> 3, c8 = (idx & 7) * 8;
        *(uint4*)(QP + r * APADH + c8) =
            *(const uint4*)(QKV + base + (size_t)(qb * 128 + r) * QKVN + c8);
    }

    int nkt = 2 * qb + 2;

    auto issue = [&](int kb, int bi) {
        uint32_t kaddr = kv_b + (uint32_t)bi * 2 * KVTILE_H * 2;
        uint32_t vaddr = kaddr + KVTILE_H * 2;
        const __half* Kg = Kg0 + (size_t)(kb * 64) * QKVN;
        const __half* Vg = Vg0 + (size_t)(kb * 64) * QKVN;
        #pragma unroll
        for (int u = 0; u < 2; u++) {
            int r = ldr + u * 32;
            cp_async16(kaddr + (uint32_t)(r * APADH + ldc) * 2, Kg + (size_t)r * QKVN + ldc);
            cp_async16(vaddr + (uint32_t)(r * APADH + ldc) * 2, Vg + (size_t)r * QKVN + ldc);
        }
    };

    issue(0, 0); cp_commit();
    issue(1, 1); cp_commit();
    __syncthreads();   // Q visible

    uint32_t qa[4][4];
    #pragma unroll
    for (int ks = 0; ks < 4; ks++)
        ldm_x4(qa[ks], qp_b + (uint32_t)((wrow + a_r) * APADH + ks * 16 + a_k8) * 2);

    float m0 = -1e30f, m1 = -1e30f, l0 = 0.f, l1 = 0.f;
    float o[8][4];
    #pragma unroll
    for (int ni = 0; ni < 8; ni++)
        #pragma unroll
        for (int e = 0; e < 4; e++) o[ni][e] = 0.f;

    #pragma unroll 1
    for (int kb = 0; kb < nkt; kb++) {
        int bi = kb % 3;
        cp_wait<1>();
        __syncthreads();
        if (kb + 2 < nkt) issue(kb + 2, (kb + 2) % 3);
        cp_commit();

        bool active = (kb * 64) <= (qb * 128 + wrow + 15);
        if (active) {
            uint32_t ks_b2 = kv_b + (uint32_t)bi * 2 * KVTILE_H * 2;
            uint32_t vs_b2 = ks_b2 + KVTILE_H * 2;

            float s[8][4];
            #pragma unroll
            for (int ni = 0; ni < 8; ni++)
                #pragma unroll
                for (int e = 0; e < 4; e++) s[ni][e] = 0.f;
            #pragma unroll
            for (int ks = 0; ks < 4; ks++) {
                #pragma unroll
                for (int nj = 0; nj < 4; nj++) {
                    uint32_t bf[4];
                    ldm_x4(bf, ks_b2 + (uint32_t)((nj * 16 + b_r) * APADH + ks * 16 + b_k8) * 2);
                    mma_f16(s[2 * nj],     qa[ks][0], qa[ks][1], qa[ks][2], qa[ks][3], bf[0], bf[1]);
                    mma_f16(s[2 * nj + 1], qa[ks][0], qa[ks][1], qa[ks][2], qa[ks][3], bf[2], bf[3]);
                }
            }

            if (kb >= 2 * qb) {
                int row0 = qb * 128 + wrow + g;
                int row1 = row0 + 8;
                #pragma unroll
                for (int ni = 0; ni < 8; ni++) {
                    int col = kb * 64 + ni * 8 + 2 * kq;
                    if (col     > row0) s[ni][0] = -1e30f;
                    if (col + 1 > row0) s[ni][1] = -1e30f;
                    if (col     > row1) s[ni][2] = -1e30f;
                    if (col + 1 > row1) s[ni][3] = -1e30f;
                }
            }

            float rm0 = -1e30f, rm1 = -1e30f;
            #pragma unroll
            for (int ni = 0; ni < 8; ni++) {
                rm0 = fmaxf(rm0, fmaxf(s[ni][0], s[ni][1]));
                rm1 = fmaxf(rm1, fmaxf(s[ni][2], s[ni][3]));
            }
            rm0 = fmaxf(rm0, __shfl_xor_sync(0xffffffffu, rm0, 1));
            rm0 = fmaxf(rm0, __shfl_xor_sync(0xffffffffu, rm0, 2));
            rm1 = fmaxf(rm1, __shfl_xor_sync(0xffffffffu, rm1, 1));
            rm1 = fmaxf(rm1, __shfl_xor_sync(0xffffffffu, rm1, 2));
            float mn0 = fmaxf(m0, rm0), mn1 = fmaxf(m1, rm1);
            float a0 = exp2f(m0 - mn0), a1 = exp2f(m1 - mn1);
            float rs0 = 0.f, rs1 = 0.f;
            uint32_t pp[8][2];
            #pragma unroll
            for (int ni = 0; ni < 8; ni++) {
                uint32_t p01 = h2exp2(pack_h2(s[ni][0] - mn0, s[ni][1] - mn0));
                uint32_t p23 = h2exp2(pack_h2(s[ni][2] - mn1, s[ni][3] - mn1));
                pp[ni][0] = p01;
                pp[ni][1] = p23;
                __half2 h01 = *reinterpret_cast<__half2*>(&p01);
                __half2 h23 = *reinterpret_cast<__half2*>(&p23);
                rs0 += __low2float(h01) + __high2float(h01);
                rs1 += __low2float(h23) + __high2float(h23);
            }
            rs0 += __shfl_xor_sync(0xffffffffu, rs0, 1);
            rs0 += __shfl_xor_sync(0xffffffffu, rs0, 2);
            rs1 += __shfl_xor_sync(0xffffffffu, rs1, 1);
            rs1 += __shfl_xor_sync(0xffffffffu, rs1, 2);
            l0 = l0 * a0 + rs0;
            l1 = l1 * a1 + rs1;
            m0 = mn0; m1 = mn1;
            #pragma unroll
            for (int ni = 0; ni < 8; ni++) {
                o[ni][0] *= a0; o[ni][1] *= a0;
                o[ni][2] *= a1; o[ni][3] *= a1;
            }

            #pragma unroll
            for (int ks2 = 0; ks2 < 4; ks2++) {
                uint32_t pa0 = pp[2 * ks2][0],     pa1 = pp[2 * ks2][1];
                uint32_t pa2 = pp[2 * ks2 + 1][0], pa3 = pp[2 * ks2 + 1][1];
                #pragma unroll
                for (int nj = 0; nj < 4; nj++) {
                    uint32_t bf[4];
                    ldm_x4_trans(bf, vs_b2 + (uint32_t)((ks2 * 16 + vt_r) * APADH + nj * 16 + vt_c8) * 2);
                    mma_f16(o[2 * nj],     pa0, pa1, pa2, pa3, bf[0], bf[1]);
                    mma_f16(o[2 * nj + 1], pa0, pa1, pa2, pa3, bf[2], bf[3]);
                }
            }
        }
    }

    float inv0 = 1.0f / l0, inv1 = 1.0f / l1;
    size_t row0 = obase + (size_t)(qb * 128 + wrow + g) * EMB;
    size_t row1 = row0 + (size_t)8 * EMB;
    #pragma unroll
    for (int ni = 0; ni < 8; ni++) {
        int col = ni * 8 + 2 * kq;
        *(uint32_t*)(O + row0 + col) = pack_h2(o[ni][0] * inv0, o[ni][1] * inv0);
        *(uint32_t*)(O + row1 + col) = pack_h2(o[ni][2] * inv1, o[ni][3] * inv1);
    }
}

// ================= launch =================
extern "C" void kernel_launch(void* const* d_in, const int* in_sizes, int n_in,
                              void* d_out, int out_size)
{
    const float* x         = (const float*)d_in[0];
    const float* Wq        = (const float*)d_in[1];
    const float* bq        = (const float*)d_in[2];
    const float* Wk        = (const float*)d_in[3];
    const float* bk        = (const float*)d_in[4];
    const float* Wv        = (const float*)d_in[5];
    const float* bv        = (const float*)d_in[6];
    const float* Wo        = (const float*)d_in[7];
    const float* bo        = (const float*)d_in[8];
    const float* W1        = (const float*)d_in[9];
    const float* b1        = (const float*)d_in[10];
    const float* W2        = (const float*)d_in[11];
    const float* b2        = (const float*)d_in[12];
    const float* ln1_scale = (const float*)d_in[13];
    const float* ln1_shift = (const float*)d_in[14];
    const float* ln2_scale = (const float*)d_in[15];
    const float* ln2_shift = (const float*)d_in[16];
    float* out = (float*)d_out;

    __half *h, *qkv, *ctx, *ff, *wtqkv, *wto, *wt1, *wt2;
    float *x2, *bqkv;
    cudaGetSymbolAddress((void**)&h,     g_h);
    cudaGetSymbolAddress((void**)&qkv,   g_qkv);
    cudaGetSymbolAddress((void**)&ctx,   g_ctx);
    cudaGetSymbolAddress((void**)&x2,    g_x2);
    cudaGetSymbolAddress((void**)&ff,    g_ff);
    cudaGetSymbolAddress((void**)&bqkv,  g_bqkv);
    cudaGetSymbolAddress((void**)&wtqkv, g_wtqkv);
    cudaGetSymbolAddress((void**)&wto,   g_wto);
    cudaGetSymbolAddress((void**)&wt1,   g_wt1);
    cudaGetSymbolAddress((void**)&wt2,   g_wt2);

    cudaFuncSetAttribute(tc_gemm,  cudaFuncAttributeMaxDynamicSharedMemorySize, GEMM_SMEM);
    cudaFuncSetAttribute(attn_mma, cudaFuncAttributeMaxDynamicSharedMemorySize, ATTN_SMEM);

    dim3 gQKV(QKVN / 128, MTOT / 128);
    dim3 gE  (EMB  / 128, MTOT / 128);
    dim3 gF  (FF   / 128, MTOT / 128);
    dim3 gA  (SEQ / 128, NHEADS, BATCH);

    prep_weights<<<12300, dim3(32, 8)>>>(Wq, Wk, Wv, Wo, W1, W2, bq, bk, bv,
                                         wtqkv, wto, wt1, wt2, bqkv);
    ln_kernel<<<MTOT / 8, 256>>>(x, ln1_scale, ln1_shift, h);
    tc_gemm<<<gQKV, 256, GEMM_SMEM>>>(h, wtqkv, bqkv, nullptr, qkv, MTOT, QKVN, EMB, 0);
    attn_mma<<<gA, 256, ATTN_SMEM>>>(qkv, ctx);
    tc_gemm<<<gE, 256, GEMM_SMEM>>>(ctx, wto, bo, x, x2, MTOT, EMB, EMB, 1);
    ln_kernel<<<MTOT / 8, 256>>>(x2, ln2_scale, ln2_shift, h);
    tc_gemm<<<gF, 256, GEMM_SMEM>>>(h, wt1, b1, nullptr, ff, MTOT, FF, EMB, 2);
    tc_gemm<<<gE, 256, GEMM_SMEM>>>(ff, wt2, b2, x2, out, MTOT, EMB, FF, 1);
}

// round 12
// speedup vs baseline: 2.2529x; 1.0213x over previous
#include <cuda_runtime.h>
#include <cuda_fp16.h>
#include <math.h>
#include <stdint.h>

#define BATCH 2
#define SEQ   2048
#define EMB   1024
#define NHEADS 16
#define HDIM  64
#define FF    4096
#define MTOT  (BATCH*SEQ)   /* 4096 rows */
#define QKVN  (3*EMB)       /* 3072 */

__device__ __forceinline__ uint32_t smem_u32(const void* p) {
    uint32_t a;
    asm("{ .reg .u64 t; cvta.to.shared.u64 t, %1; cvt.u32.u64 %0, t; }" : "=r"(a) : "l"(p));
    return a;
}
__device__ __forceinline__ void mma_f16(float c[4],
    uint32_t a0, uint32_t a1, uint32_t a2, uint32_t a3,
    uint32_t b0, uint32_t b1)
{
    asm volatile("mma.sync.aligned.m16n8k16.row.col.f32.f16.f16.f32 "
        "{%0,%1,%2,%3}, {%4,%5,%6,%7}, {%8,%9}, {%0,%1,%2,%3};"
        : "+f"(c[0]), "+f"(c[1]), "+f"(c[2]), "+f"(c[3])
        : "r"(a0), "r"(a1), "r"(a2), "r"(a3), "r"(b0), "r"(b1));
}
__device__ __forceinline__ void ldm_x4(uint32_t r[4], uint32_t saddr) {
    asm volatile("ldmatrix.sync.aligned.m8n8.x4.shared.b16 {%0,%1,%2,%3}, [%4];"
        : "=r"(r[0]), "=r"(r[1]), "=r"(r[2]), "=r"(r[3]) : "r"(saddr));
}
__device__ __forceinline__ void ldm_x4_trans(uint32_t r[4], uint32_t saddr) {
    asm volatile("ldmatrix.sync.aligned.m8n8.x4.trans.shared.b16 {%0,%1,%2,%3}, [%4];"
        : "=r"(r[0]), "=r"(r[1]), "=r"(r[2]), "=r"(r[3]) : "r"(saddr));
}
__device__ __forceinline__ void ldm_x2_trans(uint32_t r[2], uint32_t saddr) {
    asm volatile("ldmatrix.sync.aligned.m8n8.x2.trans.shared.b16 {%0,%1}, [%2];"
        : "=r"(r[0]), "=r"(r[1]) : "r"(saddr));
}
__device__ __forceinline__ void cp_async16(uint32_t saddr, const void* gptr) {
    asm volatile("cp.async.cg.shared.global [%0], [%1], 16;" :: "r"(saddr), "l"(gptr));
}
__device__ __forceinline__ void cp_commit() { asm volatile("cp.async.commit_group;" ::: "memory"); }
template<int N> __device__ __forceinline__ void cp_wait() {
    asm volatile("cp.async.wait_group %0;" :: "n"(N) : "memory");
}
__device__ __forceinline__ uint32_t pack_h2(float a, float b) {
    __half2 h = __floats2half2_rn(a, b);
    return *reinterpret_cast<uint32_t*>(&h);
}
__device__ __forceinline__ uint32_t h2exp2(uint32_t x) {
    uint32_t y;
    asm("ex2.approx.f16x2 %0, %1;" : "=r"(y) : "r"(x));
    return y;
}
__device__ __forceinline__ float tanh_fast(float x) {
    float y;
    asm("tanh.approx.f32 %0, %1;" : "=f"(y) : "f"(x));
    return y;
}

#define LOG2E 1.4426950408889634f

// ================= scratch (device globals) =================
__device__ __half g_h  [MTOT*EMB];
__device__ __half g_qkv[(size_t)MTOT*QKVN];
__device__ __half g_ctx[MTOT*EMB];
__device__ float  g_x2 [MTOT*EMB];
__device__ __half g_ff [(size_t)MTOT*FF];
__device__ __half g_wtqkv[(size_t)QKVN*EMB];
__device__ __half g_wto[EMB*EMB];
__device__ __half g_wt1[(size_t)FF*EMB];
__device__ __half g_wt2[(size_t)EMB*FF];
__device__ float  g_bqkv[QKVN];

// ================= LayerNorm (ddof=1), warp-per-row, half output =================
__global__ __launch_bounds__(256)
void ln_kernel(const float* __restrict__ x, const float* __restrict__ sc,
               const float* __restrict__ sh, __half* __restrict__ out)
{
    int row  = blockIdx.x * 8 + (threadIdx.x >> 5);
    int lane = threadIdx.x & 31;
    const float* xr = x + (size_t)row * EMB;

    float4 v[8];
    #pragma unroll
    for (int i = 0; i < 8; i++)
        v[i] = *(const float4*)(xr + lane * 4 + i * 128);

    float s = 0.f;
    #pragma unroll
    for (int i = 0; i < 8; i++) s += v[i].x + v[i].y + v[i].z + v[i].w;
    #pragma unroll
    for (int o = 16; o; o >>= 1) s += __shfl_xor_sync(0xffffffffu, s, o);
    float mean = s * (1.0f / EMB);

    float sq = 0.f;
    #pragma unroll
    for (int i = 0; i < 8; i++) {
        float d0 = v[i].x - mean, d1 = v[i].y - mean;
        float d2 = v[i].z - mean, d3 = v[i].w - mean;
        sq += d0 * d0 + d1 * d1 + d2 * d2 + d3 * d3;
    }
    #pragma unroll
    for (int o = 16; o; o >>= 1) sq += __shfl_xor_sync(0xffffffffu, sq, o);
    float rstd = rsqrtf(sq * (1.0f / (EMB - 1)) + 1e-5f);

    #pragma unroll
    for (int i = 0; i < 8; i++) {
        int c = lane * 4 + i * 128;
        float4 scv = *(const float4*)(sc + c);
        float4 shv = *(const float4*)(sh + c);
        float r0 = scv.x * (v[i].x - mean) * rstd + shv.x;
        float r1 = scv.y * (v[i].y - mean) * rstd + shv.y;
        float r2 = scv.z * (v[i].z - mean) * rstd + shv.z;
        float r3 = scv.w * (v[i].w - mean) * rstd + shv.w;
        uint2 st = { pack_h2(r0, r1), pack_h2(r2, r3) };
        *(uint2*)(out + (size_t)row * EMB + c) = st;
    }
}

// ================= fused weight prep =================
__global__ __launch_bounds__(256)
void prep_weights(const float* __restrict__ Wq, const float* __restrict__ Wk,
                  const float* __restrict__ Wv, const float* __restrict__ Wo,
                  const float* __restrict__ W1, const float* __restrict__ W2,
                  const float* __restrict__ bq, const float* __restrict__ bk,
                  const float* __restrict__ bv,
                  __half* __restrict__ wtqkv, __half* __restrict__ wto,
                  __half* __restrict__ wt1, __half* __restrict__ wt2,
                  float* __restrict__ bqkv)
{
    int bid = blockIdx.x;
    int tx = threadIdx.x, ty = threadIdx.y;
    if (bid >= 12288) {
        int i = (bid - 12288) * 256 + ty * 32 + tx;
        if (i < EMB)            bqkv[i] = bq[i] * (0.125f * LOG2E);
        else if (i < 2 * EMB)   bqkv[i] = bk[i - EMB];
        else if (i < 3 * EMB)   bqkv[i] = bv[i - 2 * EMB];
        return;
    }
    const float* W; __half* Wt; int K, N, tiles_x, t; float scale = 1.f;
    if (bid < 3072) {
        int w = bid >> 10; t = bid & 1023;
        W = (w == 0) ? Wq : (w == 1) ? Wk : Wv;
        Wt = wtqkv + (size_t)w * EMB * EMB;
        K = EMB; N = EMB; tiles_x = 32;
        if (w == 0) scale = 0.125f * LOG2E;
    } else if (bid < 4096) {
        t = bid - 3072; W = Wo; Wt = wto; K = EMB; N = EMB; tiles_x = 32;
    } else if (bid < 8192) {
        t = bid - 4096; W = W1; Wt = wt1; K = EMB; N = FF; tiles_x = 128;
    } else {
        t = bid - 8192; W = W2; Wt = wt2; K = FF; N = EMB; tiles_x = 32;
    }
    int x0 = (t % tiles_x) * 32, y0 = (t / tiles_x) * 32;
    __shared__ float tile[32][33];
    #pragma unroll
    for (int j = 0; j < 32; j += 8)
        tile[ty + j][tx] = W[(size_t)(y0 + ty + j) * N + x0 + tx];
    __syncthreads();
    #pragma unroll
    for (int j = 0; j < 32; j += 8)
        Wt[(size_t)(x0 + ty + j) * K + y0 + tx] = __float2half(tile[tx][ty + j] * scale);
}

// ================= fp16 mma.sync GEMM =================
#define PADH 40
#define TILE_H (128*PADH)
#define STAGE_B (2*TILE_H*2)
#define GEMM_SMEM (4*STAGE_B)

__global__ __launch_bounds__(256, 2)
void tc_gemm(const __half* __restrict__ A, const __half* __restrict__ Bt,
             const float* __restrict__ bias, const float* __restrict__ res,
             void* __restrict__ Cv, int M, int N, int K, int mode)
{
    extern __shared__ __half smh[];
    uint32_t sb = smem_u32(smh);

    int tid  = threadIdx.x;
    int lane = tid & 31, wid = tid >> 5;
    int g    = lane >> 2;
    int kq   = lane & 3;
    int wm   = wid & 1;
    int wn   = wid >> 1;
    int bcol = blockIdx.x * 128, brow = blockIdx.y * 128;

    int a_r  = (lane & 7) + ((lane >> 3) & 1) * 8;
    int a_k8 = (lane >> 4) * 8;
    int b_r  = (lane & 7) + (lane >> 4) * 8;
    int b_k8 = ((lane >> 3) & 1) * 8;

    const __half* Ap = A  + (size_t)brow * K;
    const __half* Bp = Bt + (size_t)bcol * K;

    int lr[2], lc[2];
    #pragma unroll
    for (int u = 0; u < 2; u++) {
        int idx = tid + u * 256;
        lr[u] = idx >> 2;
        lc[u] = idx & 3;
    }

    float acc[4][4][4];
    #pragma unroll
    for (int mi = 0; mi < 4; mi++)
        #pragma unroll
        for (int ni = 0; ni < 4; ni++)
            #pragma unroll
            for (int e = 0; e < 4; e++) acc[mi][ni][e] = 0.f;

    int nk = K >> 5;

    #pragma unroll
    for (int s = 0; s < 3; s++) {
        uint32_t abase = sb + (uint32_t)s * STAGE_B;
        uint32_t bbase = abase + TILE_H * 2;
        const __half* Ag = Ap + s * 32;
        const __half* Bg = Bp + s * 32;
        #pragma unroll
        for (int u = 0; u < 2; u++) {
            cp_async16(abase + (uint32_t)(lr[u] * 80 + lc[u] * 16), Ag + (size_t)lr[u] * K + lc[u] * 8);
            cp_async16(bbase + (uint32_t)(lr[u] * 80 + lc[u] * 16), Bg + (size_t)lr[u] * K + lc[u] * 8);
        }
        cp_commit();
    }

    #pragma unroll 1
    for (int kt = 0; kt < nk; kt++) {
        cp_wait<2>();
        __syncthreads();

        if (kt + 3 < nk) {
            int s = (kt + 3) & 3;
            uint32_t abase = sb + (uint32_t)s * STAGE_B;
            uint32_t bbase = abase + TILE_H * 2;
            const __half* Ag = Ap + (kt + 3) * 32;
            const __half* Bg = Bp + (kt + 3) * 32;
            #pragma unroll
            for (int u = 0; u < 2; u++) {
                cp_async16(abase + (uint32_t)(lr[u] * 80 + lc[u] * 16), Ag + (size_t)lr[u] * K + lc[u] * 8);
                cp_async16(bbase + (uint32_t)(lr[u] * 80 + lc[u] * 16), Bg + (size_t)lr[u] * K + lc[u] * 8);
            }
        }
        cp_commit();

        uint32_t As_b = sb + (uint32_t)(kt & 3) * STAGE_B;
        uint32_t Bs_b = As_b + TILE_H * 2;
        #pragma unroll
        for (int ks = 0; ks < 2; ks++) {
            int k0 = ks * 16;
            uint32_t af[4][4], bf[4][2];
            #pragma unroll
            for (int mi = 0; mi < 4; mi++)
                ldm_x4(af[mi], As_b + (uint32_t)((wm * 64 + mi * 16 + a_r) * PADH + k0 + a_k8) * 2);
            #pragma unroll
            for (int nj = 0; nj < 2; nj++)
                ldm_x4(&bf[2 * nj][0], Bs_b + (uint32_t)((wn * 32 + nj * 16 + b_r) * PADH + k0 + b_k8) * 2);
            #pragma unroll
            for (int mi = 0; mi < 4; mi++)
                #pragma unroll
                for (int ni = 0; ni < 4; ni++)
                    mma_f16(acc[mi][ni], af[mi][0], af[mi][1], af[mi][2], af[mi][3],
                            bf[ni][0], bf[ni][1]);
        }
    }

    #pragma unroll
    for (int mi = 0; mi < 4; mi++) {
        #pragma unroll
        for (int ni = 0; ni < 4; ni++) {
            int row = brow + wm * 64 + mi * 16 + g;
            int col = bcol + wn * 32 + ni * 8 + 2 * kq;
            #pragma unroll
            for (int half_ = 0; half_ < 2; half_++) {
                int r = row + half_ * 8;
                float v0 = acc[mi][ni][half_ * 2 + 0] + bias[col];
                float v1 = acc[mi][ni][half_ * 2 + 1] + bias[col + 1];
                if (mode == 1) {
                    v0 += res[(size_t)r * N + col];
                    v1 += res[(size_t)r * N + col + 1];
                    float2 o2 = { v0, v1 };
                    *(float2*)((float*)Cv + (size_t)r * N + col) = o2;
                } else {
                    if (mode == 2) {
                        float x0 = v0, x1 = v1;
                        v0 = 0.5f * x0 * (1.f + tanh_fast(0.7978845608028654f *
                                                      (x0 + 0.044715f * x0 * x0 * x0)));
                        v1 = 0.5f * x1 * (1.f + tanh_fast(0.7978845608028654f *
                                                      (x1 + 0.044715f * x1 * x1 * x1)));
                    }
                    *(uint32_t*)((__half*)Cv + (size_t)r * N + col) = pack_h2(v0, v1);
                }
            }
        }
    }
}

// ================= Causal flash attention: ones-column row sums =================
// Vt padding cols 64..71 hold 1.0; P @ [V|1] accumulates both ctx and row-sum l
// in TC fragments with identical rescaling — no per-tile sum reduction.
#define APADH 72
#define KVTILE_H (64*APADH)
#define ATTN_SMEM ((128 + 6*64)*APADH*2)   /* 73728 bytes */

__global__ __launch_bounds__(256, 2)
void attn_mma(const __half* __restrict__ QKV, __half* __restrict__ O)
{
    extern __shared__ __half smA[];
    __half* QP = smA;
    uint32_t qp_b = smem_u32(QP);
    uint32_t kv_b = qp_b + 128 * APADH * 2;   // 3 x (K|V) buffers

    int tid = threadIdx.x, lane = tid & 31, w = tid >> 5;
    int g = lane >> 2, kq = lane & 3;
    int qb = gridDim.x - 1 - blockIdx.x;
    int h = blockIdx.y, b = blockIdx.z;
    size_t base  = ((size_t)b * SEQ) * QKVN + h * HDIM;
    size_t obase = ((size_t)b * SEQ) * EMB + h * HDIM;
    int wrow = w * 16;

    int a_r  = (lane & 7) + ((lane >> 3) & 1) * 8;
    int a_k8 = (lane >> 4) * 8;
    int b_r  = (lane & 7) + (lane >> 4) * 8;
    int b_k8 = ((lane >> 3) & 1) * 8;
    int vt_r  = (lane & 7) + ((lane >> 3) & 1) * 8;
    int vt_c8 = (lane >> 4) * 8;
    int v2_r  = lane & 15;   // x2 ldmatrix row (lanes 0-15 used; keep all valid)

    const __half* Kg0 = QKV + base + EMB;
    const __half* Vg0 = QKV + base + 2 * EMB;
    int ldr = tid >> 3, ldc = (tid & 7) * 8;

    // stage Q tile
    #pragma unroll
    for (int u = 0; u < 4; u++) {
        int idx = tid + u * 256;
        int r = idx >> 3, c8 = (idx & 7) * 8;
        *(uint4*)(QP + r * APADH + c8) =
            *(const uint4*)(QKV + base + (size_t)(qb * 128 + r) * QKVN + c8);
    }
    // initialize ones-columns (cols 64..71) of all 3 V buffers (cp.async never touches them)
    if (tid < 192) {
        int buf = tid >> 6, row = tid & 63;
        __half* vt = smA + 128 * APADH + (size_t)(buf * 2 + 1) * KVTILE_H + row * APADH + 64;
        uint32_t one2 = pack_h2(1.f, 1.f);
        uint4 ones = { one2, one2, one2, one2 };
        *(uint4*)vt = ones;
    }

    int nkt = 2 * qb + 2;

    auto issue = [&](int kb, int bi) {
        uint32_t kaddr = kv_b + (uint32_t)bi * 2 * KVTILE_H * 2;
        uint32_t vaddr = kaddr + KVTILE_H * 2;
        const __half* Kg = Kg0 + (size_t)(kb * 64) * QKVN;
        const __half* Vg = Vg0 + (size_t)(kb * 64) * QKVN;
        #pragma unroll
        for (int u = 0; u < 2; u++) {
            int r = ldr + u * 32;
            cp_async16(kaddr + (uint32_t)(r * APADH + ldc) * 2, Kg + (size_t)r * QKVN + ldc);
            cp_async16(vaddr + (uint32_t)(r * APADH + ldc) * 2, Vg + (size_t)r * QKVN + ldc);
        }
    };

    issue(0, 0); cp_commit();
    issue(1, 1); cp_commit();
    __syncthreads();   // Q + ones visible

    uint32_t qa[4][4];
    #pragma unroll
    for (int ks = 0; ks < 4; ks++)
        ldm_x4(qa[ks], qp_b + (uint32_t)((wrow + a_r) * APADH + ks * 16 + a_k8) * 2);

    float m0 = -1e30f, m1 = -1e30f;
    float o[8][4], ox[4];
    #pragma unroll
    for (int ni = 0; ni < 8; ni++)
        #pragma unroll
        for (int e = 0; e < 4; e++) o[ni][e] = 0.f;
    #pragma unroll
    for (int e = 0; e < 4; e++) ox[e] = 0.f;

    #pragma unroll 1
    for (int kb = 0; kb < nkt; kb++) {
        int bi = kb % 3;
        cp_wait<1>();
        __syncthreads();
        if (kb + 2 < nkt) issue(kb + 2, (kb + 2) % 3);
        cp_commit();

        bool active = (kb * 64) <= (qb * 128 + wrow + 15);
        if (active) {
            uint32_t ks_b2 = kv_b + (uint32_t)bi * 2 * KVTILE_H * 2;
            uint32_t vs_b2 = ks_b2 + KVTILE_H * 2;

            float s[8][4];
            #pragma unroll
            for (int ni = 0; ni < 8; ni++)
                #pragma unroll
                for (int e = 0; e < 4; e++) s[ni][e] = 0.f;
            #pragma unroll
            for (int ks = 0; ks < 4; ks++) {
                #pragma unroll
                for (int nj = 0; nj < 4; nj++) {
                    uint32_t bf[4];
                    ldm_x4(bf, ks_b2 + (uint32_t)((nj * 16 + b_r) * APADH + ks * 16 + b_k8) * 2);
                    mma_f16(s[2 * nj],     qa[ks][0], qa[ks][1], qa[ks][2], qa[ks][3], bf[0], bf[1]);
                    mma_f16(s[2 * nj + 1], qa[ks][0], qa[ks][1], qa[ks][2], qa[ks][3], bf[2], bf[3]);
                }
            }

            if (kb >= 2 * qb) {
                int row0 = qb * 128 + wrow + g;
                int row1 = row0 + 8;
                #pragma unroll
                for (int ni = 0; ni < 8; ni++) {
                    int col = kb * 64 + ni * 8 + 2 * kq;
                    if (col     > row0) s[ni][0] = -1e30f;
                    if (col + 1 > row0) s[ni][1] = -1e30f;
                    if (col     > row1) s[ni][2] = -1e30f;
                    if (col + 1 > row1) s[ni][3] = -1e30f;
                }
            }

            float rm0 = -1e30f, rm1 = -1e30f;
            #pragma unroll
            for (int ni = 0; ni < 8; ni++) {
                rm0 = fmaxf(rm0, fmaxf(s[ni][0], s[ni][1]));
                rm1 = fmaxf(rm1, fmaxf(s[ni][2], s[ni][3]));
            }
            rm0 = fmaxf(rm0, __shfl_xor_sync(0xffffffffu, rm0, 1));
            rm0 = fmaxf(rm0, __shfl_xor_sync(0xffffffffu, rm0, 2));
            rm1 = fmaxf(rm1, __shfl_xor_sync(0xffffffffu, rm1, 1));
            rm1 = fmaxf(rm1, __shfl_xor_sync(0xffffffffu, rm1, 2));
            float mn0 = fmaxf(m0, rm0), mn1 = fmaxf(m1, rm1);
            float a0 = exp2f(m0 - mn0), a1 = exp2f(m1 - mn1);
            uint32_t pp[8][2];
            #pragma unroll
            for (int ni = 0; ni < 8; ni++) {
                pp[ni][0] = h2exp2(pack_h2(s[ni][0] - mn0, s[ni][1] - mn0));
                pp[ni][1] = h2exp2(pack_h2(s[ni][2] - mn1, s[ni][3] - mn1));
            }
            m0 = mn0; m1 = mn1;
            #pragma unroll
            for (int ni = 0; ni < 8; ni++) {
                o[ni][0] *= a0; o[ni][1] *= a0;
                o[ni][2] *= a1; o[ni][3] *= a1;
            }
            ox[0] *= a0; ox[1] *= a0; ox[2] *= a1; ox[3] *= a1;

            // ctx/l += P @ [V | 1]
            #pragma unroll
            for (int ks2 = 0; ks2 < 4; ks2++) {
                uint32_t pa0 = pp[2 * ks2][0],     pa1 = pp[2 * ks2][1];
                uint32_t pa2 = pp[2 * ks2 + 1][0], pa3 = pp[2 * ks2 + 1][1];
                #pragma unroll
                for (int nj = 0; nj < 4; nj++) {
                    uint32_t bf[4];
                    ldm_x4_trans(bf, vs_b2 + (uint32_t)((ks2 * 16 + vt_r) * APADH + nj * 16 + vt_c8) * 2);
                    mma_f16(o[2 * nj],     pa0, pa1, pa2, pa3, bf[0], bf[1]);
                    mma_f16(o[2 * nj + 1], pa0, pa1, pa2, pa3, bf[2], bf[3]);
                }
                uint32_t bf2[2];
                ldm_x2_trans(bf2, vs_b2 + (uint32_t)((ks2 * 16 + v2_r) * APADH + 64) * 2);
                mma_f16(ox, pa0, pa1, pa2, pa3, bf2[0], bf2[1]);
            }
        }
    }

    float inv0 = 1.0f / ox[0], inv1 = 1.0f / ox[2];
    size_t row0 = obase + (size_t)(qb * 128 + wrow + g) * EMB;
    size_t row1 = row0 + (size_t)8 * EMB;
    #pragma unroll
    for (int ni = 0; ni < 8; ni++) {
        int col = ni * 8 + 2 * kq;
        *(uint32_t*)(O + row0 + col) = pack_h2(o[ni][0] * inv0, o[ni][1] * inv0);
        *(uint32_t*)(O + row1 + col) = pack_h2(o[ni][2] * inv1, o[ni][3] * inv1);
    }
}

// ================= launch =================
extern "C" void kernel_launch(void* const* d_in, const int* in_sizes, int n_in,
                              void* d_out, int out_size)
{
    const float* x         = (const float*)d_in[0];
    const float* Wq        = (const float*)d_in[1];
    const float* bq        = (const float*)d_in[2];
    const float* Wk        = (const float*)d_in[3];
    const float* bk        = (const float*)d_in[4];
    const float* Wv        = (const float*)d_in[5];
    const float* bv        = (const float*)d_in[6];
    const float* Wo        = (const float*)d_in[7];
    const float* bo        = (const float*)d_in[8];
    const float* W1        = (const float*)d_in[9];
    const float* b1        = (const float*)d_in[10];
    const float* W2        = (const float*)d_in[11];
    const float* b2        = (const float*)d_in[12];
    const float* ln1_scale = (const float*)d_in[13];
    const float* ln1_shift = (const float*)d_in[14];
    const float* ln2_scale = (const float*)d_in[15];
    const float* ln2_shift = (const float*)d_in[16];
    float* out = (float*)d_out;

    __half *h, *qkv, *ctx, *ff, *wtqkv, *wto, *wt1, *wt2;
    float *x2, *bqkv;
    cudaGetSymbolAddress((void**)&h,     g_h);
    cudaGetSymbolAddress((void**)&qkv,   g_qkv);
    cudaGetSymbolAddress((void**)&ctx,   g_ctx);
    cudaGetSymbolAddress((void**)&x2,    g_x2);
    cudaGetSymbolAddress((void**)&ff,    g_ff);
    cudaGetSymbolAddress((void**)&bqkv,  g_bqkv);
    cudaGetSymbolAddress((void**)&wtqkv, g_wtqkv);
    cudaGetSymbolAddress((void**)&wto,   g_wto);
    cudaGetSymbolAddress((void**)&wt1,   g_wt1);
    cudaGetSymbolAddress((void**)&wt2,   g_wt2);

    cudaFuncSetAttribute(tc_gemm,  cudaFuncAttributeMaxDynamicSharedMemorySize, GEMM_SMEM);
    cudaFuncSetAttribute(attn_mma, cudaFuncAttributeMaxDynamicSharedMemorySize, ATTN_SMEM);

    dim3 gQKV(QKVN / 128, MTOT / 128);
    dim3 gE  (EMB  / 128, MTOT / 128);
    dim3 gF  (FF   / 128, MTOT / 128);
    dim3 gA  (SEQ / 128, NHEADS, BATCH);

    prep_weights<<<12300, dim3(32, 8)>>>(Wq, Wk, Wv, Wo, W1, W2, bq, bk, bv,
                                         wtqkv, wto, wt1, wt2, bqkv);
    ln_kernel<<<MTOT / 8, 256>>>(x, ln1_scale, ln1_shift, h);
    tc_gemm<<<gQKV, 256, GEMM_SMEM>>>(h, wtqkv, bqkv, nullptr, qkv, MTOT, QKVN, EMB, 0);
    attn_mma<<<gA, 256, ATTN_SMEM>>>(qkv, ctx);
    tc_gemm<<<gE, 256, GEMM_SMEM>>>(ctx, wto, bo, x, x2, MTOT, EMB, EMB, 1);
    ln_kernel<<<MTOT / 8, 256>>>(x2, ln2_scale, ln2_shift, h);
    tc_gemm<<<gF, 256, GEMM_SMEM>>>(h, wt1, b1, nullptr, ff, MTOT, FF, EMB, 2);
    tc_gemm<<<gE, 256, GEMM_SMEM>>>(ff, wt2, b2, x2, out, MTOT, EMB, FF, 1);
}